// round 6
// baseline (speedup 1.0000x reference)
#include <cuda_runtime.h>
#include <cuda_bf16.h>
#include <math.h>
#include <stdint.h>

// Problem constants
#define Bn   64
#define Td   256
#define Tp   1024
#define NB   (Bn * 256)
#define NEGV (-1e9f)
#define AL   __align__(256)

// ---------------- device scratch ----------------
__device__ AL __nv_bfloat16 g_F1h[Td * Tp];
__device__ AL __nv_bfloat16 g_F2h[Tp * Td];
__device__ AL __nv_bfloat16 g_Xph[Bn * Tp * 128], g_Xpl[Bn * Tp * 128];
__device__ AL __nv_bfloat16 g_Xsh[Bn * Td * 128], g_Xsl[Bn * Td * 128];
__device__ AL __nv_bfloat16 g_Wp1h[384 * 128], g_Wp1l[384 * 128];
__device__ AL __nv_bfloat16 g_Wp2h[384 * 128], g_Wp2l[384 * 128];
__device__ AL float g_bp1[384], g_bp2[384];
__device__ AL __nv_bfloat16 g_Wodh[128 * 128], g_Wodl[128 * 128];
__device__ AL __nv_bfloat16 g_Woph[128 * 128], g_Wopl[128 * 128];
__device__ AL float g_P1[Bn * Tp * 384];
__device__ AL float g_P2[Bn * Td * 384];
__device__ AL __nv_bfloat16 g_KV1th[NB * Tp], g_KV1tl[NB * Tp];
__device__ AL __nv_bfloat16 g_KV2th[NB * Td], g_KV2tl[NB * Td];
__device__ AL float g_base1[NB], g_base2[NB];   // interleaved: [b*256 + 2d + {0,1}]
__device__ AL __nv_bfloat16 g_Y1h[Bn * Td * 128], g_Y1l[Bn * Td * 128];
__device__ AL __nv_bfloat16 g_Y2h[Bn * Tp * 128], g_Y2l[Bn * Tp * 128];
__device__ AL unsigned g_ob1[Bn * 128], g_ob2[Bn * 128];

// ---------------- helpers ----------------
__device__ __forceinline__ unsigned f2key(float f) {
    unsigned u = __float_as_uint(f);
    return (u & 0x80000000u) ? ~u : (u | 0x80000000u);
}
__device__ __forceinline__ float key2f(unsigned u) {
    unsigned b = (u & 0x80000000u) ? (u ^ 0x80000000u) : ~u;
    return __uint_as_float(b);
}
__device__ __forceinline__ void mma16816(float* d, const uint32_t* a,
                                         uint32_t b0, uint32_t b1) {
    asm volatile(
        "mma.sync.aligned.m16n8k16.row.col.f32.bf16.bf16.f32 "
        "{%0,%1,%2,%3}, {%4,%5,%6,%7}, {%8,%9}, {%0,%1,%2,%3};"
        : "+f"(d[0]), "+f"(d[1]), "+f"(d[2]), "+f"(d[3])
        : "r"(a[0]), "r"(a[1]), "r"(a[2]), "r"(a[3]), "r"(b0), "r"(b1));
}
__device__ __forceinline__ void ldsm4(uint32_t* r, const __nv_bfloat16* p) {
    uint32_t a = (uint32_t)__cvta_generic_to_shared(p);
    asm volatile("ldmatrix.sync.aligned.m8n8.x4.shared.b16 {%0,%1,%2,%3}, [%4];"
                 : "=r"(r[0]), "=r"(r[1]), "=r"(r[2]), "=r"(r[3]) : "r"(a));
}
__device__ __forceinline__ void cpa16(__nv_bfloat16* s, const __nv_bfloat16* g) {
    uint32_t a = (uint32_t)__cvta_generic_to_shared(s);
    asm volatile("cp.async.cg.shared.global [%0], [%1], 16;\n" :: "r"(a), "l"(g));
}
#define CP_COMMIT() asm volatile("cp.async.commit_group;\n" ::: "memory")
#define CP_WAIT1()  asm volatile("cp.async.wait_group 1;\n" ::: "memory")

// ---------------- bf16 GEMM, 3-stage cp.async pipeline, fused epilogues ----------------
// C[M,N] = sum of A_ta @ B_tb^T (skipping ta=1&tb=1).
// MODE 0: write fp32 C (+bias inF0). MODE 1: fused AFT y (inF0=P q-src, inF1=base,
// out bf16 hi/lo Y). MODE 2: fused masked max (inI=mask, outU=ob, ldx=SEQ).
// Tile 128x128x32, 256 threads, 8 warps (4m x 2n), warp tile 32x64.
// smem row r, 16B chunk c: phys chunk = c ^ ((r>>1)&3). 3 stages, dynamic smem.
template <int TA, int TB, int MODE>
__global__ __launch_bounds__(256) void gemm_bf(
    const __nv_bfloat16* __restrict__ A0, const __nv_bfloat16* __restrict__ A1,
    const __nv_bfloat16* __restrict__ B0, const __nv_bfloat16* __restrict__ B1,
    const float* __restrict__ inF0, const float* __restrict__ inF1,
    const int* __restrict__ inI,
    float* __restrict__ outF, __nv_bfloat16* __restrict__ outH,
    __nv_bfloat16* __restrict__ outL, unsigned* __restrict__ outU,
    int K, int lda, int ldb, int ldx)
{
    extern __shared__ __nv_bfloat16 smem[];
    constexpr int TERM = TA + TB;
    constexpr int TILE = 128 * 32;

    const int tid  = threadIdx.x;
    const int lane = tid & 31;
    const int wid  = tid >> 5;
    const int wm   = (wid >> 1) * 32;
    const int wn   = (wid & 1) * 64;
    const int brow = blockIdx.y * 128;
    const int bcol = blockIdx.x * 128;

    const int lr  = tid >> 2;
    const int lc  = tid & 3;
    const int so0 = lr * 32 + ((lc ^ ((lr >> 1) & 3)) * 8);
    const int so1 = (lr + 64) * 32 + ((lc ^ (((lr + 64) >> 1) & 3)) * 8);

    const __nv_bfloat16* gA0 = A0 + (size_t)(brow + lr) * lda + lc * 8;
    const __nv_bfloat16* gA1 = (TA > 1) ? (A1 + (size_t)(brow + lr) * lda + lc * 8) : A0;
    const __nv_bfloat16* gB0 = B0 + (size_t)(bcol + lr) * ldb + lc * 8;
    const __nv_bfloat16* gB1 = (TB > 1) ? (B1 + (size_t)(bcol + lr) * ldb + lc * 8) : B0;
    const size_t a64 = (size_t)64 * lda, b64 = (size_t)64 * ldb;

    auto issue = [&](int k0, int s) {
        __nv_bfloat16* sb = smem + s * (TERM * TILE);
        cpa16(sb + so0, gA0 + k0);
        cpa16(sb + so1, gA0 + a64 + k0);
        if (TA > 1) {
            cpa16(sb + TILE + so0, gA1 + k0);
            cpa16(sb + TILE + so1, gA1 + a64 + k0);
        }
        __nv_bfloat16* sB = sb + TA * TILE;
        cpa16(sB + so0, gB0 + k0);
        cpa16(sB + so1, gB0 + b64 + k0);
        if (TB > 1) {
            cpa16(sB + TILE + so0, gB1 + k0);
            cpa16(sB + TILE + so1, gB1 + b64 + k0);
        }
        CP_COMMIT();
    };

    const int iters = K >> 5;
    issue(0, 0);
    issue(32, 1);

    float acc[2][8][4] = {};

    const int arow_b = (lane & 7) + ((lane >> 3) & 1) * 8;
    const int achk_b = (lane >> 4);
    const int brow_b = (lane & 7) + (lane >> 4) * 8;
    const int bchk_b = (lane >> 3) & 1;

    for (int i = 0; i < iters; i++) {
        CP_WAIT1();
        __syncthreads();
        if (i + 2 < iters) issue(32 * (i + 2), (i + 2) % 3);

        const __nv_bfloat16* sb  = smem + (i % 3) * (TERM * TILE);
        const __nv_bfloat16* sA0 = sb;
        const __nv_bfloat16* sA1 = sb + TILE;          // valid if TA>1
        const __nv_bfloat16* sB0 = sb + TA * TILE;
        const __nv_bfloat16* sB1 = sB0 + TILE;         // valid if TB>1

        #pragma unroll
        for (int ck = 0; ck < 2; ck++) {
            uint32_t af[TA][2][4];
            #pragma unroll
            for (int mt = 0; mt < 2; mt++) {
                int row = wm + mt * 16 + arow_b;
                int chk = 2 * ck + achk_b;
                int off = row * 32 + ((chk ^ ((row >> 1) & 3)) * 8);
                ldsm4(af[0][mt], &sA0[off]);
                if (TA > 1) ldsm4(af[TA - 1][mt], &sA1[off]);
            }
            #pragma unroll
            for (int ntp = 0; ntp < 4; ntp++) {
                int row = wn + ntp * 16 + brow_b;
                int chk = 2 * ck + bchk_b;
                int off = row * 32 + ((chk ^ ((row >> 1) & 3)) * 8);
                uint32_t bf0[4], bf1[4];
                ldsm4(bf0, &sB0[off]);
                if (TB > 1) ldsm4(bf1, &sB1[off]);
                #pragma unroll
                for (int mt = 0; mt < 2; mt++) {
                    mma16816(acc[mt][2 * ntp],     af[0][mt], bf0[0], bf0[1]);
                    mma16816(acc[mt][2 * ntp + 1], af[0][mt], bf0[2], bf0[3]);
                    if (TB > 1) {
                        mma16816(acc[mt][2 * ntp],     af[0][mt], bf1[0], bf1[1]);
                        mma16816(acc[mt][2 * ntp + 1], af[0][mt], bf1[2], bf1[3]);
                    }
                    if (TA > 1) {
                        mma16816(acc[mt][2 * ntp],     af[TA - 1][mt], bf0[0], bf0[1]);
                        mma16816(acc[mt][2 * ntp + 1], af[TA - 1][mt], bf0[2], bf0[3]);
                    }
                }
            }
        }
    }

    const int g = lane >> 2;
    const int c = lane & 3;

    if (MODE == 0) {
        #pragma unroll
        for (int mt = 0; mt < 2; mt++) {
            #pragma unroll
            for (int nt = 0; nt < 8; nt++) {
                int row = brow + wm + mt * 16 + g;
                int col = bcol + wn + nt * 8 + 2 * c;
                float bx = inF0 ? inF0[col] : 0.f;
                float by = inF0 ? inF0[col + 1] : 0.f;
                float2 v0, v1;
                v0.x = acc[mt][nt][0] + bx; v0.y = acc[mt][nt][1] + by;
                v1.x = acc[mt][nt][2] + bx; v1.y = acc[mt][nt][3] + by;
                *(float2*)&outF[(size_t)row * ldx + col]       = v0;
                *(float2*)&outF[(size_t)(row + 8) * ldx + col] = v1;
            }
        }
    } else if (MODE == 1) {
        // acc pair = (num, den) for (row, d). col = b*256 + 2d.
        const int M = gridDim.y * 128;
        const int b = bcol >> 8;
        #pragma unroll
        for (int mt = 0; mt < 2; mt++) {
            #pragma unroll
            for (int nt = 0; nt < 8; nt++) {
                int row = brow + wm + mt * 16 + g;
                int col = bcol + wn + nt * 8 + 2 * c;
                int d = (col & 255) >> 1;
                float2 bs = *(const float2*)&inF1[col];
                #pragma unroll
                for (int r2 = 0; r2 < 2; r2++) {
                    int rr = row + 8 * r2;
                    float num = acc[mt][nt][2 * r2]     + bs.x;
                    float den = acc[mt][nt][2 * r2 + 1] + bs.y;
                    float q = inF0[((size_t)b * M + rr) * 384 + 256 + d];
                    float sg = 1.f / (1.f + expf(-q));
                    float y = sg * num / den;
                    __nv_bfloat16 h = __float2bfloat16(y);
                    size_t o = ((size_t)b * M + rr) * 128 + d;
                    outH[o] = h;
                    outL[o] = __float2bfloat16(y - __bfloat162float(h));
                }
            }
        }
    } else {
        // masked max over rows, atomicMax into ob[b*128+col]
        const int SEQ = ldx;
        const int b = brow / SEQ;
        int msk[2][2];
        #pragma unroll
        for (int mt = 0; mt < 2; mt++) {
            msk[mt][0] = inI[brow + wm + mt * 16 + g];
            msk[mt][1] = inI[brow + wm + mt * 16 + g + 8];
        }
        #pragma unroll
        for (int nt = 0; nt < 8; nt++) {
            float m0 = -3.0e38f, m1 = -3.0e38f;
            #pragma unroll
            for (int mt = 0; mt < 2; mt++) {
                if (msk[mt][0]) { m0 = fmaxf(m0, acc[mt][nt][0]); m1 = fmaxf(m1, acc[mt][nt][1]); }
                if (msk[mt][1]) { m0 = fmaxf(m0, acc[mt][nt][2]); m1 = fmaxf(m1, acc[mt][nt][3]); }
            }
            #pragma unroll
            for (int off = 4; off < 32; off <<= 1) {
                m0 = fmaxf(m0, __shfl_xor_sync(0xffffffffu, m0, off));
                m1 = fmaxf(m1, __shfl_xor_sync(0xffffffffu, m1, off));
            }
            if (g == 0) {
                int col = wn + nt * 8 + 2 * c;
                if (m0 > -2.9e38f) atomicMax(&outU[b * 128 + col],     f2key(m0));
                if (m1 > -2.9e38f) atomicMax(&outU[b * 128 + col + 1], f2key(m1));
            }
        }
    }
}

// ---------------- small kernels ----------------
__global__ void k_init(unsigned* ob1, unsigned* ob2, float* base1, float* base2) {
    int i = blockIdx.x * 256 + threadIdx.x;
    if (i < Bn * 128) {
        unsigned k = f2key(NEGV);
        ob1[i] = k; ob2[i] = k;
    }
    if (i < NB) { base1[i] = 0.f; base2[i] = 0.f; }
}

__global__ void k_expf(const float* __restrict__ pb, __nv_bfloat16* __restrict__ F1,
                       __nv_bfloat16* __restrict__ F2) {
    __shared__ float s[32][33];
    int j0 = blockIdx.x * 32, i0 = blockIdx.y * 32;
    int tx = threadIdx.x & 31, ty = threadIdx.x >> 5;
    #pragma unroll
    for (int r = ty; r < 32; r += 8) {
        float v = expf(pb[(i0 + r) * 1024 + j0 + tx]) - 1.0f;
        F1[(i0 + r) * Tp + j0 + tx] = __float2bfloat16(v);
        s[r][tx] = v;
    }
    __syncthreads();
    #pragma unroll
    for (int r = ty; r < 32; r += 8)
        F2[(j0 + r) * Td + i0 + tx] = __float2bfloat16(s[tx][r]);
}

// fp32 -> (hi,lo) bf16 split; 8 floats per thread, 16B stores
__global__ void k_split(const float* __restrict__ x, __nv_bfloat16* __restrict__ h,
                        __nv_bfloat16* __restrict__ l, int n8) {
    int i = blockIdx.x * 256 + threadIdx.x;
    if (i >= n8) return;
    float4 v0 = ((const float4*)x)[2 * i];
    float4 v1 = ((const float4*)x)[2 * i + 1];
    float f[8] = {v0.x, v0.y, v0.z, v0.w, v1.x, v1.y, v1.z, v1.w};
    uint32_t hh[4], ll[4];
    #pragma unroll
    for (int j = 0; j < 4; j++) {
        __nv_bfloat162 hp, lp;
        hp.x = __float2bfloat16(f[2 * j]);
        hp.y = __float2bfloat16(f[2 * j + 1]);
        lp.x = __float2bfloat16(f[2 * j]     - __bfloat162float(hp.x));
        lp.y = __float2bfloat16(f[2 * j + 1] - __bfloat162float(hp.y));
        hh[j] = *(uint32_t*)&hp;
        ll[j] = *(uint32_t*)&lp;
    }
    ((uint4*)h)[i] = make_uint4(hh[0], hh[1], hh[2], hh[3]);
    ((uint4*)l)[i] = make_uint4(ll[0], ll[1], ll[2], ll[3]);
}

__global__ void k_pack_split(const float* __restrict__ Wk, const float* __restrict__ bk,
                             const float* __restrict__ Wv, const float* __restrict__ bv,
                             const float* __restrict__ Wq, const float* __restrict__ bq,
                             __nv_bfloat16* __restrict__ Wh, __nv_bfloat16* __restrict__ Wl,
                             float* __restrict__ bp) {
    int i = blockIdx.x * 256 + threadIdx.x;
    if (i < 384 * 128) {
        int r = i >> 7, c = i & 127;
        const float* s = (r < 128) ? Wk : ((r < 256) ? Wv : Wq);
        float w = s[(r & 127) * 128 + c];
        __nv_bfloat16 h = __float2bfloat16(w);
        Wh[i] = h;
        Wl[i] = __float2bfloat16(w - __bfloat162float(h));
    }
    if (i < 384) bp[i] = (i < 128) ? bk[i] : ((i < 256) ? bv[i - 128] : bq[i - 256]);
}

// Build KV transposed (INTERLEAVED rows: b*256 + 2d + {0=ev,1=e}) + fp32 column sums
template <int SEQ>
__global__ __launch_bounds__(256) void k_buildKVt(const float* __restrict__ P,
        const int* __restrict__ mask, __nv_bfloat16* __restrict__ KVh,
        __nv_bfloat16* __restrict__ KVl, float* __restrict__ base) {
    __shared__ float s_ev[32][129];
    __shared__ float s_e[32][129];
    int b = blockIdx.x, j0 = blockIdx.y * 32, t = threadIdx.x;
    #pragma unroll
    for (int i = 0; i < 16; i++) {
        int idx = t + 256 * i;
        int j = idx >> 7, d = idx & 127;
        size_t prow = ((size_t)b * SEQ + j0 + j) * 384;
        float kp = P[prow + d];
        float vp = P[prow + 128 + d];
        float m  = (float)mask[b * SEQ + j0 + j];
        float e  = m * expf(kp);
        s_ev[j][d] = e * vp;
        s_e[j][d]  = e;
    }
    __syncthreads();
    {
        float s = 0.f;
        if (t < 128) {
            for (int j = 0; j < 32; j++) s += s_ev[j][t];
            atomicAdd(&base[b * 256 + 2 * t], s);
        } else {
            for (int j = 0; j < 32; j++) s += s_e[j][t - 128];
            atomicAdd(&base[b * 256 + 2 * (t - 128) + 1], s);
        }
    }
    #pragma unroll
    for (int i = 0; i < 16; i++) {
        int idx = t + 256 * i;
        int d = idx >> 5, j = idx & 31;
        float v1 = s_ev[j][d], v2 = s_e[j][d];
        size_t o1 = ((size_t)(b * 256 + 2 * d)) * SEQ + j0 + j;
        size_t o2 = ((size_t)(b * 256 + 2 * d + 1)) * SEQ + j0 + j;
        __nv_bfloat16 h1 = __float2bfloat16(v1), h2 = __float2bfloat16(v2);
        KVh[o1] = h1; KVl[o1] = __float2bfloat16(v1 - __bfloat162float(h1));
        KVh[o2] = h2; KVl[o2] = __float2bfloat16(v2 - __bfloat162float(h2));
    }
}

__global__ void k_out(const unsigned* __restrict__ ob1, const unsigned* __restrict__ ob2,
                      const float* __restrict__ bpd, const float* __restrict__ bpp,
                      float* __restrict__ out) {
    int i = blockIdx.x * 256 + threadIdx.x;
    if (i < Bn * 128) {
        int t = i & 127;
        out[i]            = key2f(ob1[i]) + bpd[t];
        out[Bn * 128 + i] = key2f(ob2[i]) + bpp[t];
    }
}

// ---------------- launch ----------------
#define SYM(p, s) cudaGetSymbolAddress((void**)&p, s)
#define NUL_F (const float*)0
#define NUL_I (const int*)0
#define NUL_H (__nv_bfloat16*)0

extern "C" void kernel_launch(void* const* d_in, const int* in_sizes, int n_in,
                              void* d_out, int out_size) {
    const float* smiles  = (const float*)d_in[0];
    const float* protein = (const float*)d_in[1];
    const int*   smask   = (const int*)d_in[2];
    const int*   pmask   = (const int*)d_in[3];
    const float* pb      = (const float*)d_in[4];
    const float* Wqd = (const float*)d_in[5],  *bqd = (const float*)d_in[6];
    const float* Wkp = (const float*)d_in[7],  *bkp = (const float*)d_in[8];
    const float* Wvp = (const float*)d_in[9],  *bvp = (const float*)d_in[10];
    const float* Wqp = (const float*)d_in[11], *bqp = (const float*)d_in[12];
    const float* Wkd = (const float*)d_in[13], *bkd = (const float*)d_in[14];
    const float* Wvd = (const float*)d_in[15], *bvd = (const float*)d_in[16];
    const float* Wpd = (const float*)d_in[17], *bpd = (const float*)d_in[18];
    const float* Wpp = (const float*)d_in[19], *bpp = (const float*)d_in[20];
    float* out = (float*)d_out;

    __nv_bfloat16 *F1h, *F2h, *Xph, *Xpl, *Xsh, *Xsl, *Wp1h, *Wp1l, *Wp2h, *Wp2l;
    __nv_bfloat16 *Wodh, *Wodl, *Woph, *Wopl, *KV1th, *KV1tl, *KV2th, *KV2tl;
    __nv_bfloat16 *Y1h, *Y1l, *Y2h, *Y2l;
    float *bp1, *bp2, *P1, *P2, *base1, *base2;
    unsigned *ob1, *ob2;
    SYM(F1h, g_F1h);   SYM(F2h, g_F2h);
    SYM(Xph, g_Xph);   SYM(Xpl, g_Xpl);   SYM(Xsh, g_Xsh);   SYM(Xsl, g_Xsl);
    SYM(Wp1h, g_Wp1h); SYM(Wp1l, g_Wp1l); SYM(Wp2h, g_Wp2h); SYM(Wp2l, g_Wp2l);
    SYM(bp1, g_bp1);   SYM(bp2, g_bp2);
    SYM(Wodh, g_Wodh); SYM(Wodl, g_Wodl); SYM(Woph, g_Woph); SYM(Wopl, g_Wopl);
    SYM(P1, g_P1);     SYM(P2, g_P2);
    SYM(KV1th, g_KV1th); SYM(KV1tl, g_KV1tl); SYM(KV2th, g_KV2th); SYM(KV2tl, g_KV2tl);
    SYM(base1, g_base1); SYM(base2, g_base2);
    SYM(Y1h, g_Y1h);   SYM(Y1l, g_Y1l);   SYM(Y2h, g_Y2h);   SYM(Y2l, g_Y2l);
    SYM(ob1, g_ob1);   SYM(ob2, g_ob2);

    // smem: stage = (TA+TB)*128*32*2 bytes; 3 stages
    const int SM3 = 3 * 3 * 128 * 32 * 2;   // TERM=3 -> 72KB
    const int SM4 = 4 * 3 * 128 * 32 * 2;   // TERM=4 -> 96KB
    cudaFuncSetAttribute(gemm_bf<2, 2, 0>, cudaFuncAttributeMaxDynamicSharedMemorySize, SM4);
    cudaFuncSetAttribute(gemm_bf<1, 2, 1>, cudaFuncAttributeMaxDynamicSharedMemorySize, SM3);
    cudaFuncSetAttribute(gemm_bf<2, 2, 2>, cudaFuncAttributeMaxDynamicSharedMemorySize, SM4);

    // init + batch-independent precompute
    k_init<<<NB / 256, 256>>>(ob1, ob2, base1, base2);
    k_expf<<<dim3(Tp / 32, Td / 32), 256>>>(pb, F1h, F2h);
    k_split<<<(Bn * Tp * 128 / 8 + 255) / 256, 256>>>(protein, Xph, Xpl, Bn * Tp * 128 / 8);
    k_split<<<(Bn * Td * 128 / 8 + 255) / 256, 256>>>(smiles, Xsh, Xsl, Bn * Td * 128 / 8);
    k_split<<<(128 * 128 / 8 + 255) / 256, 256>>>(Wpd, Wodh, Wodl, 128 * 128 / 8);
    k_split<<<(128 * 128 / 8 + 255) / 256, 256>>>(Wpp, Woph, Wopl, 128 * 128 / 8);
    k_pack_split<<<192, 256>>>(Wkp, bkp, Wvp, bvp, Wqp, bqp, Wp1h, Wp1l, bp1);
    k_pack_split<<<192, 256>>>(Wkd, bkd, Wvd, bvd, Wqd, bqd, Wp2h, Wp2l, bp2);

    // fused projections: [k; v; q]
    gemm_bf<2, 2, 0><<<dim3(3, (Bn * Tp) / 128), 256, SM4>>>(
        Xph, Xpl, Wp1h, Wp1l, bp1, NUL_F, NUL_I, P1, NUL_H, NUL_H, (unsigned*)0,
        128, 128, 128, 384);
    gemm_bf<2, 2, 0><<<dim3(3, (Bn * Td) / 128), 256, SM4>>>(
        Xsh, Xsl, Wp2h, Wp2l, bp2, NUL_F, NUL_I, P2, NUL_H, NUL_H, (unsigned*)0,
        128, 128, 128, 384);

    // build interleaved transposed KV + exact column-sum base
    k_buildKVt<Tp><<<dim3(Bn, Tp / 32), 256>>>(P1, pmask, KV1th, KV1tl, base1);
    k_buildKVt<Td><<<dim3(Bn, Td / 32), 256>>>(P2, smask, KV2th, KV2tl, base2);

    // main AFT GEMMs with fused y-epilogue (writes Y bf16 hi/lo directly)
    gemm_bf<1, 2, 1><<<dim3(NB / 128, Td / 128), 256, SM3>>>(
        F1h, NUL_H, KV1th, KV1tl, P2, base1, NUL_I, (float*)0, Y1h, Y1l, (unsigned*)0,
        Tp, Tp, Tp, 0);
    gemm_bf<1, 2, 1><<<dim3(NB / 128, Tp / 128), 256, SM3>>>(
        F2h, NUL_H, KV2th, KV2tl, P1, base2, NUL_I, (float*)0, Y2h, Y2l, (unsigned*)0,
        Td, Td, Td, 0);

    // output projections with fused masked-max epilogue
    gemm_bf<2, 2, 2><<<dim3(1, (Bn * Td) / 128), 256, SM4>>>(
        Y1h, Y1l, Wodh, Wodl, NUL_F, NUL_F, smask, (float*)0, NUL_H, NUL_H, ob1,
        128, 128, 128, Td);
    gemm_bf<2, 2, 2><<<dim3(1, (Bn * Tp) / 128), 256, SM4>>>(
        Y2h, Y2l, Woph, Wopl, NUL_F, NUL_F, pmask, (float*)0, NUL_H, NUL_H, ob2,
        128, 128, 128, Tp);

    // decode + add output bias
    k_out<<<(Bn * 128 + 255) / 256, 256>>>(ob1, ob2, bpd, bpp, out);
}

// round 8
// speedup vs baseline: 1.4854x; 1.4854x over previous
#include <cuda_runtime.h>
#include <cuda_fp16.h>
#include <math.h>
#include <stdint.h>

// Problem constants
#define Bn   64
#define Td   256
#define Tp   1024
#define NB   (Bn * 256)
#define NEGV (-1e9f)
#define AL   __align__(256)

// ---------------- device scratch ----------------
__device__ AL __half g_F1h[Td * Tp];
__device__ AL __half g_F2h[Tp * Td];
__device__ AL __half g_Xph[Bn * Tp * 128];
__device__ AL __half g_Xsh[Bn * Td * 128];
__device__ AL __half g_Wp1h[384 * 128], g_Wp1l[384 * 128];
__device__ AL __half g_Wp2h[384 * 128], g_Wp2l[384 * 128];
__device__ AL float g_bp1[384], g_bp2[384];
__device__ AL __half g_Wodh[128 * 128], g_Wodl[128 * 128];
__device__ AL __half g_Woph[128 * 128], g_Wopl[128 * 128];
__device__ AL float g_P1[Bn * Tp * 384];
__device__ AL float g_P2[Bn * Td * 384];
__device__ AL __half g_KV1th[NB * Tp];
__device__ AL __half g_KV2th[NB * Td];
__device__ AL float g_base1[NB], g_base2[NB];   // interleaved [b*256 + 2d + {0,1}]
__device__ AL __half g_Y1h[Bn * Td * 128];
__device__ AL __half g_Y2h[Bn * Tp * 128];
__device__ AL unsigned g_ob1[Bn * 128], g_ob2[Bn * 128];

// ---------------- helpers ----------------
__device__ __forceinline__ unsigned f2key(float f) {
    unsigned u = __float_as_uint(f);
    return (u & 0x80000000u) ? ~u : (u | 0x80000000u);
}
__device__ __forceinline__ float key2f(unsigned u) {
    unsigned b = (u & 0x80000000u) ? (u ^ 0x80000000u) : ~u;
    return __uint_as_float(b);
}
__device__ __forceinline__ void mma16816(float* d, const uint32_t* a,
                                         uint32_t b0, uint32_t b1) {
    asm volatile(
        "mma.sync.aligned.m16n8k16.row.col.f32.f16.f16.f32 "
        "{%0,%1,%2,%3}, {%4,%5,%6,%7}, {%8,%9}, {%0,%1,%2,%3};"
        : "+f"(d[0]), "+f"(d[1]), "+f"(d[2]), "+f"(d[3])
        : "r"(a[0]), "r"(a[1]), "r"(a[2]), "r"(a[3]), "r"(b0), "r"(b1));
}
__device__ __forceinline__ void ldsm4(uint32_t* r, const __half* p) {
    uint32_t a = (uint32_t)__cvta_generic_to_shared(p);
    asm volatile("ldmatrix.sync.aligned.m8n8.x4.shared.b16 {%0,%1,%2,%3}, [%4];"
                 : "=r"(r[0]), "=r"(r[1]), "=r"(r[2]), "=r"(r[3]) : "r"(a));
}

// ---------------- fp16 tensor-core GEMM, fused epilogues ----------------
// C[M,N] = sum of A_ta @ B_tb^T (skipping ta=1&tb=1 term).
// MODE 0: fp32 C + bias (inF0), ldc=ldx.
// MODE 1: fused AFT y: acc pairs (num,den); y=sigmoid(q)*(num+bs)/(den+bs) -> fp16 Y.
// MODE 2: fused masked max -> atomicMax outU (inI=mask, ldx=SEQ).
// Tile 128x128x32, 256 threads, 8 warps (4m x 2n), warp tile 32x64.
// smem: row r, 16B chunk c -> phys chunk = c ^ ((r>>1)&3).
template <int TA, int TB, int MODE>
__global__ __launch_bounds__(256, 1) void gemm_hf(
    const __half* __restrict__ A0, const __half* __restrict__ A1,
    const __half* __restrict__ B0, const __half* __restrict__ B1,
    const float* __restrict__ inF0, const float* __restrict__ inF1,
    const int* __restrict__ inI,
    float* __restrict__ outF, __half* __restrict__ outH, unsigned* __restrict__ outU,
    int K, int lda, int ldb, int ldx)
{
    __shared__ __half SA[TA][128 * 32];
    __shared__ __half SB[TB][128 * 32];

    const int tid  = threadIdx.x;
    const int lane = tid & 31;
    const int wid  = tid >> 5;
    const int wm   = (wid >> 1) * 32;
    const int wn   = (wid & 1) * 64;
    const int brow = blockIdx.y * 128;
    const int bcol = blockIdx.x * 128;

    const int lr  = tid >> 2;
    const int lc  = tid & 3;
    const int so0 = lr * 32 + ((lc ^ ((lr >> 1) & 3)) * 8);
    const int so1 = (lr + 64) * 32 + ((lc ^ (((lr + 64) >> 1) & 3)) * 8);

    const __half* gA0 = A0 + (size_t)(brow + lr) * lda + lc * 8;
    const __half* gA1 = (TA > 1) ? (A1 + (size_t)(brow + lr) * lda + lc * 8) : A0;
    const __half* gB0 = B0 + (size_t)(bcol + lr) * ldb + lc * 8;
    const __half* gB1 = (TB > 1) ? (B1 + (size_t)(bcol + lr) * ldb + lc * 8) : B0;
    const size_t a64 = (size_t)64 * lda, b64 = (size_t)64 * ldb;

    uint4 ra0[2], ra1[2], rb0[2], rb1[2];
    ra0[0] = *(const uint4*)(gA0); ra0[1] = *(const uint4*)(gA0 + a64);
    if (TA > 1) { ra1[0] = *(const uint4*)(gA1); ra1[1] = *(const uint4*)(gA1 + a64); }
    rb0[0] = *(const uint4*)(gB0); rb0[1] = *(const uint4*)(gB0 + b64);
    if (TB > 1) { rb1[0] = *(const uint4*)(gB1); rb1[1] = *(const uint4*)(gB1 + b64); }

    float acc[2][8][4] = {};

    const int arow_b = (lane & 7) + ((lane >> 3) & 1) * 8;
    const int achk_b = (lane >> 4);
    const int brow_b = (lane & 7) + (lane >> 4) * 8;
    const int bchk_b = (lane >> 3) & 1;

    for (int k0 = 0; k0 < K; k0 += 32) {
        *(uint4*)&SA[0][so0] = ra0[0]; *(uint4*)&SA[0][so1] = ra0[1];
        if (TA > 1) { *(uint4*)&SA[1][so0] = ra1[0]; *(uint4*)&SA[1][so1] = ra1[1]; }
        *(uint4*)&SB[0][so0] = rb0[0]; *(uint4*)&SB[0][so1] = rb0[1];
        if (TB > 1) { *(uint4*)&SB[1][so0] = rb1[0]; *(uint4*)&SB[1][so1] = rb1[1]; }
        __syncthreads();

        if (k0 + 32 < K) {
            ra0[0] = *(const uint4*)(gA0 + k0 + 32);
            ra0[1] = *(const uint4*)(gA0 + a64 + k0 + 32);
            if (TA > 1) {
                ra1[0] = *(const uint4*)(gA1 + k0 + 32);
                ra1[1] = *(const uint4*)(gA1 + a64 + k0 + 32);
            }
            rb0[0] = *(const uint4*)(gB0 + k0 + 32);
            rb0[1] = *(const uint4*)(gB0 + b64 + k0 + 32);
            if (TB > 1) {
                rb1[0] = *(const uint4*)(gB1 + k0 + 32);
                rb1[1] = *(const uint4*)(gB1 + b64 + k0 + 32);
            }
        }

        #pragma unroll
        for (int ck = 0; ck < 2; ck++) {
            uint32_t af[TA][2][4];
            #pragma unroll
            for (int mt = 0; mt < 2; mt++) {
                int row = wm + mt * 16 + arow_b;
                int chk = 2 * ck + achk_b;
                int off = row * 32 + ((chk ^ ((row >> 1) & 3)) * 8);
                ldsm4(af[0][mt], &SA[0][off]);
                if (TA > 1) ldsm4(af[TA - 1][mt], &SA[TA - 1][off]);
            }
            #pragma unroll
            for (int ntp = 0; ntp < 4; ntp++) {
                int row = wn + ntp * 16 + brow_b;
                int chk = 2 * ck + bchk_b;
                int off = row * 32 + ((chk ^ ((row >> 1) & 3)) * 8);
                uint32_t bf0[4], bf1[4];
                ldsm4(bf0, &SB[0][off]);
                if (TB > 1) ldsm4(bf1, &SB[TB - 1][off]);
                #pragma unroll
                for (int mt = 0; mt < 2; mt++) {
                    mma16816(acc[mt][2 * ntp],     af[0][mt], bf0[0], bf0[1]);
                    mma16816(acc[mt][2 * ntp + 1], af[0][mt], bf0[2], bf0[3]);
                    if (TB > 1) {
                        mma16816(acc[mt][2 * ntp],     af[0][mt], bf1[0], bf1[1]);
                        mma16816(acc[mt][2 * ntp + 1], af[0][mt], bf1[2], bf1[3]);
                    }
                    if (TA > 1) {
                        mma16816(acc[mt][2 * ntp],     af[TA - 1][mt], bf0[0], bf0[1]);
                        mma16816(acc[mt][2 * ntp + 1], af[TA - 1][mt], bf0[2], bf0[3]);
                    }
                }
            }
        }
        __syncthreads();
    }

    const int g = lane >> 2;
    const int c = lane & 3;

    if (MODE == 0) {
        #pragma unroll
        for (int mt = 0; mt < 2; mt++) {
            #pragma unroll
            for (int nt = 0; nt < 8; nt++) {
                int row = brow + wm + mt * 16 + g;
                int col = bcol + wn + nt * 8 + 2 * c;
                float bx = inF0[col], by = inF0[col + 1];
                float2 v0, v1;
                v0.x = acc[mt][nt][0] + bx; v0.y = acc[mt][nt][1] + by;
                v1.x = acc[mt][nt][2] + bx; v1.y = acc[mt][nt][3] + by;
                *(float2*)&outF[(size_t)row * ldx + col]       = v0;
                *(float2*)&outF[(size_t)(row + 8) * ldx + col] = v1;
            }
        }
    } else if (MODE == 1) {
        const int M = gridDim.y * 128;
        const int b = bcol >> 8;
        #pragma unroll
        for (int mt = 0; mt < 2; mt++) {
            #pragma unroll
            for (int nt = 0; nt < 8; nt++) {
                int row = brow + wm + mt * 16 + g;
                int col = bcol + wn + nt * 8 + 2 * c;
                int d = (col & 255) >> 1;
                float2 bs = *(const float2*)&inF1[col];
                #pragma unroll
                for (int r2 = 0; r2 < 2; r2++) {
                    int rr = row + 8 * r2;
                    float num = acc[mt][nt][2 * r2]     + bs.x;
                    float den = acc[mt][nt][2 * r2 + 1] + bs.y;
                    float q = inF0[((size_t)b * M + rr) * 384 + 256 + d];
                    float sg = 1.f / (1.f + expf(-q));
                    float y = sg * num / den;
                    outH[((size_t)b * M + rr) * 128 + d] = __float2half(y);
                }
            }
        }
    } else {
        const int SEQ = ldx;
        const int b = brow / SEQ;
        int msk[2][2];
        #pragma unroll
        for (int mt = 0; mt < 2; mt++) {
            msk[mt][0] = inI[brow + wm + mt * 16 + g];
            msk[mt][1] = inI[brow + wm + mt * 16 + g + 8];
        }
        #pragma unroll
        for (int nt = 0; nt < 8; nt++) {
            float m0 = -3.0e38f, m1 = -3.0e38f;
            #pragma unroll
            for (int mt = 0; mt < 2; mt++) {
                if (msk[mt][0]) { m0 = fmaxf(m0, acc[mt][nt][0]); m1 = fmaxf(m1, acc[mt][nt][1]); }
                if (msk[mt][1]) { m0 = fmaxf(m0, acc[mt][nt][2]); m1 = fmaxf(m1, acc[mt][nt][3]); }
            }
            #pragma unroll
            for (int off = 4; off < 32; off <<= 1) {
                m0 = fmaxf(m0, __shfl_xor_sync(0xffffffffu, m0, off));
                m1 = fmaxf(m1, __shfl_xor_sync(0xffffffffu, m1, off));
            }
            if (g == 0) {
                int col = wn + nt * 8 + 2 * c;
                if (m0 > -2.9e38f) atomicMax(&outU[b * 128 + col],     f2key(m0));
                if (m1 > -2.9e38f) atomicMax(&outU[b * 128 + col + 1], f2key(m1));
            }
        }
    }
}

// ---------------- small kernels ----------------
__global__ void k_init(unsigned* ob1, unsigned* ob2, float* base1, float* base2) {
    int i = blockIdx.x * 256 + threadIdx.x;
    if (i < Bn * 128) {
        unsigned k = f2key(NEGV);
        ob1[i] = k; ob2[i] = k;
    }
    if (i < NB) { base1[i] = 0.f; base2[i] = 0.f; }
}

__global__ void k_expf(const float* __restrict__ pb, __half* __restrict__ F1,
                       __half* __restrict__ F2) {
    __shared__ float s[32][33];
    int j0 = blockIdx.x * 32, i0 = blockIdx.y * 32;
    int tx = threadIdx.x & 31, ty = threadIdx.x >> 5;
    #pragma unroll
    for (int r = ty; r < 32; r += 8) {
        float v = expf(pb[(i0 + r) * 1024 + j0 + tx]) - 1.0f;
        F1[(i0 + r) * Tp + j0 + tx] = __float2half(v);
        s[r][tx] = v;
    }
    __syncthreads();
    #pragma unroll
    for (int r = ty; r < 32; r += 8)
        F2[(j0 + r) * Td + i0 + tx] = __float2half(s[tx][r]);
}

// fp32 -> fp16 convert; 8 floats per thread, 16B stores
__global__ void k_half(const float* __restrict__ x, __half* __restrict__ h, int n8) {
    int i = blockIdx.x * 256 + threadIdx.x;
    if (i >= n8) return;
    float4 v0 = ((const float4*)x)[2 * i];
    float4 v1 = ((const float4*)x)[2 * i + 1];
    uint32_t hh[4];
    __half2 p;
    p = __floats2half2_rn(v0.x, v0.y); hh[0] = *(uint32_t*)&p;
    p = __floats2half2_rn(v0.z, v0.w); hh[1] = *(uint32_t*)&p;
    p = __floats2half2_rn(v1.x, v1.y); hh[2] = *(uint32_t*)&p;
    p = __floats2half2_rn(v1.z, v1.w); hh[3] = *(uint32_t*)&p;
    ((uint4*)h)[i] = make_uint4(hh[0], hh[1], hh[2], hh[3]);
}

// fp32 -> (hi, lo) fp16 split
__global__ void k_split(const float* __restrict__ x, __half* __restrict__ h,
                        __half* __restrict__ l, int n) {
    int i = blockIdx.x * 256 + threadIdx.x;
    if (i >= n) return;
    float w = x[i];
    __half hi = __float2half(w);
    h[i] = hi;
    l[i] = __float2half(w - __half2float(hi));
}

__global__ void k_pack_split(const float* __restrict__ Wk, const float* __restrict__ bk,
                             const float* __restrict__ Wv, const float* __restrict__ bv,
                             const float* __restrict__ Wq, const float* __restrict__ bq,
                             __half* __restrict__ Wh, __half* __restrict__ Wl,
                             float* __restrict__ bp) {
    int i = blockIdx.x * 256 + threadIdx.x;
    if (i < 384 * 128) {
        int r = i >> 7, c = i & 127;
        const float* s = (r < 128) ? Wk : ((r < 256) ? Wv : Wq);
        float w = s[(r & 127) * 128 + c];
        __half h = __float2half(w);
        Wh[i] = h;
        Wl[i] = __float2half(w - __half2float(h));
    }
    if (i < 384) bp[i] = (i < 128) ? bk[i] : ((i < 256) ? bv[i - 128] : bq[i - 256]);
}

// Build KV transposed (INTERLEAVED rows: b*256 + 2d + {0=ev,1=e}) fp16 + fp32 col sums
template <int SEQ>
__global__ __launch_bounds__(256) void k_buildKVt(const float* __restrict__ P,
        const int* __restrict__ mask, __half* __restrict__ KVh, float* __restrict__ base) {
    __shared__ float s_ev[32][129];
    __shared__ float s_e[32][129];
    int b = blockIdx.x, j0 = blockIdx.y * 32, t = threadIdx.x;
    #pragma unroll
    for (int i = 0; i < 16; i++) {
        int idx = t + 256 * i;
        int j = idx >> 7, d = idx & 127;
        size_t prow = ((size_t)b * SEQ + j0 + j) * 384;
        float kp = P[prow + d];
        float vp = P[prow + 128 + d];
        float m  = (float)mask[b * SEQ + j0 + j];
        float e  = m * expf(kp);
        s_ev[j][d] = e * vp;
        s_e[j][d]  = e;
    }
    __syncthreads();
    {
        float s = 0.f;
        if (t < 128) {
            for (int j = 0; j < 32; j++) s += s_ev[j][t];
            atomicAdd(&base[b * 256 + 2 * t], s);
        } else {
            for (int j = 0; j < 32; j++) s += s_e[j][t - 128];
            atomicAdd(&base[b * 256 + 2 * (t - 128) + 1], s);
        }
    }
    #pragma unroll
    for (int i = 0; i < 16; i++) {
        int idx = t + 256 * i;
        int d = idx >> 5, j = idx & 31;
        KVh[((size_t)(b * 256 + 2 * d)) * SEQ + j0 + j]     = __float2half(s_ev[j][d]);
        KVh[((size_t)(b * 256 + 2 * d + 1)) * SEQ + j0 + j] = __float2half(s_e[j][d]);
    }
}

__global__ void k_out(const unsigned* __restrict__ ob1, const unsigned* __restrict__ ob2,
                      const float* __restrict__ bpd, const float* __restrict__ bpp,
                      float* __restrict__ out) {
    int i = blockIdx.x * 256 + threadIdx.x;
    if (i < Bn * 128) {
        int t = i & 127;
        out[i]            = key2f(ob1[i]) + bpd[t];
        out[Bn * 128 + i] = key2f(ob2[i]) + bpp[t];
    }
}

// ---------------- launch ----------------
#define SYM(p, s) cudaGetSymbolAddress((void**)&p, s)
#define NUL_F (const float*)0
#define NUL_I (const int*)0
#define NUL_H (const __half*)0

extern "C" void kernel_launch(void* const* d_in, const int* in_sizes, int n_in,
                              void* d_out, int out_size) {
    const float* smiles  = (const float*)d_in[0];
    const float* protein = (const float*)d_in[1];
    const int*   smask   = (const int*)d_in[2];
    const int*   pmask   = (const int*)d_in[3];
    const float* pb      = (const float*)d_in[4];
    const float* Wqd = (const float*)d_in[5],  *bqd = (const float*)d_in[6];
    const float* Wkp = (const float*)d_in[7],  *bkp = (const float*)d_in[8];
    const float* Wvp = (const float*)d_in[9],  *bvp = (const float*)d_in[10];
    const float* Wqp = (const float*)d_in[11], *bqp = (const float*)d_in[12];
    const float* Wkd = (const float*)d_in[13], *bkd = (const float*)d_in[14];
    const float* Wvd = (const float*)d_in[15], *bvd = (const float*)d_in[16];
    const float* Wpd = (const float*)d_in[17], *bpd = (const float*)d_in[18];
    const float* Wpp = (const float*)d_in[19], *bpp = (const float*)d_in[20];
    float* out = (float*)d_out;

    __half *F1h, *F2h, *Xph, *Xsh, *Wp1h, *Wp1l, *Wp2h, *Wp2l;
    __half *Wodh, *Wodl, *Woph, *Wopl, *KV1th, *KV2th, *Y1h, *Y2h;
    float *bp1, *bp2, *P1, *P2, *base1, *base2;
    unsigned *ob1, *ob2;
    SYM(F1h, g_F1h);   SYM(F2h, g_F2h);
    SYM(Xph, g_Xph);   SYM(Xsh, g_Xsh);
    SYM(Wp1h, g_Wp1h); SYM(Wp1l, g_Wp1l); SYM(Wp2h, g_Wp2h); SYM(Wp2l, g_Wp2l);
    SYM(bp1, g_bp1);   SYM(bp2, g_bp2);
    SYM(Wodh, g_Wodh); SYM(Wodl, g_Wodl); SYM(Woph, g_Woph); SYM(Wopl, g_Wopl);
    SYM(P1, g_P1);     SYM(P2, g_P2);
    SYM(KV1th, g_KV1th); SYM(KV2th, g_KV2th);
    SYM(base1, g_base1); SYM(base2, g_base2);
    SYM(Y1h, g_Y1h);   SYM(Y2h, g_Y2h);
    SYM(ob1, g_ob1);   SYM(ob2, g_ob2);

    // init + batch-independent precompute
    k_init<<<NB / 256, 256>>>(ob1, ob2, base1, base2);
    k_expf<<<dim3(Tp / 32, Td / 32), 256>>>(pb, F1h, F2h);
    k_half<<<(Bn * Tp * 128 / 8 + 255) / 256, 256>>>(protein, Xph, Bn * Tp * 128 / 8);
    k_half<<<(Bn * Td * 128 / 8 + 255) / 256, 256>>>(smiles, Xsh, Bn * Td * 128 / 8);
    k_split<<<(128 * 128 + 255) / 256, 256>>>(Wpd, Wodh, Wodl, 128 * 128);
    k_split<<<(128 * 128 + 255) / 256, 256>>>(Wpp, Woph, Wopl, 128 * 128);
    k_pack_split<<<192, 256>>>(Wkp, bkp, Wvp, bvp, Wqp, bqp, Wp1h, Wp1l, bp1);
    k_pack_split<<<192, 256>>>(Wkd, bkd, Wvd, bvd, Wqd, bqd, Wp2h, Wp2l, bp2);

    // fused projections: [k; v; q]  (X fp16 @ W hi/lo, 2 products)
    gemm_hf<1, 2, 0><<<dim3(3, (Bn * Tp) / 128), 256>>>(
        Xph, NUL_H, Wp1h, Wp1l, bp1, NUL_F, NUL_I, P1, (__half*)0, (unsigned*)0,
        128, 128, 128, 384);
    gemm_hf<1, 2, 0><<<dim3(3, (Bn * Td) / 128), 256>>>(
        Xsh, NUL_H, Wp2h, Wp2l, bp2, NUL_F, NUL_I, P2, (__half*)0, (unsigned*)0,
        128, 128, 128, 384);

    // build interleaved transposed KV (fp16) + exact column-sum base
    k_buildKVt<Tp><<<dim3(Bn, Tp / 32), 256>>>(P1, pmask, KV1th, base1);
    k_buildKVt<Td><<<dim3(Bn, Td / 32), 256>>>(P2, smask, KV2th, base2);

    // main AFT GEMMs (single product F @ KV) with fused y-epilogue
    gemm_hf<1, 1, 1><<<dim3(NB / 128, Td / 128), 256>>>(
        F1h, NUL_H, KV1th, NUL_H, P2, base1, NUL_I, (float*)0, Y1h, (unsigned*)0,
        Tp, Tp, Tp, 0);
    gemm_hf<1, 1, 1><<<dim3(NB / 128, Tp / 128), 256>>>(
        F2h, NUL_H, KV2th, NUL_H, P1, base2, NUL_I, (float*)0, Y2h, (unsigned*)0,
        Td, Td, Td, 0);

    // output projections (Y fp16 @ Wo hi/lo, 2 products) with fused masked-max
    gemm_hf<1, 2, 2><<<dim3(1, (Bn * Td) / 128), 256>>>(
        Y1h, NUL_H, Wodh, Wodl, NUL_F, NUL_F, smask, (float*)0, (__half*)0, ob1,
        128, 128, 128, Td);
    gemm_hf<1, 2, 2><<<dim3(1, (Bn * Tp) / 128), 256>>>(
        Y2h, NUL_H, Woph, Wopl, NUL_F, NUL_F, pmask, (float*)0, (__half*)0, ob2,
        128, 128, 128, Tp);

    // decode + add output bias
    k_out<<<(Bn * 128 + 255) / 256, 256>>>(ob1, ob2, bpd, bpp, out);
}

// round 10
// speedup vs baseline: 1.6327x; 1.0992x over previous
#include <cuda_runtime.h>
#include <cuda_fp16.h>
#include <math.h>
#include <stdint.h>

// Problem constants
#define Bn   64
#define Td   256
#define Tp   1024
#define NB   (Bn * 256)
#define NEGV (-1e9f)
#define AL   __align__(256)

// ---------------- device scratch ----------------
__device__ AL __half g_F1h[Td * Tp];
__device__ AL __half g_F2h[Tp * Td];
__device__ AL __half g_Xph[Bn * Tp * 128];
__device__ AL __half g_Xsh[Bn * Td * 128];
__device__ AL __half g_Wp1h[384 * 128], g_Wp1l[384 * 128];   // rows: k0,v0,k1,v1,...,q0..q127
__device__ AL __half g_Wp2h[384 * 128], g_Wp2l[384 * 128];
__device__ AL float g_bp1[384], g_bp2[384];
__device__ AL __half g_Wodh[128 * 128], g_Wodl[128 * 128];
__device__ AL __half g_Woph[128 * 128], g_Wopl[128 * 128];
__device__ AL float g_Q1[Bn * Tp * 128];    // dense q projections
__device__ AL float g_Q2[Bn * Td * 128];
__device__ AL __half g_KV1th[NB * Tp];      // rows b*256+2d(ev)/2d+1(e), cols j
__device__ AL __half g_KV2th[NB * Td];
__device__ AL float g_base1[NB], g_base2[NB];   // interleaved [b*256 + 2d + {0,1}]
__device__ AL __half g_Y1h[Bn * Td * 128];
__device__ AL __half g_Y2h[Bn * Tp * 128];
__device__ AL unsigned g_ob1[Bn * 128], g_ob2[Bn * 128];

// ---------------- helpers ----------------
__device__ __forceinline__ unsigned f2key(float f) {
    unsigned u = __float_as_uint(f);
    return (u & 0x80000000u) ? ~u : (u | 0x80000000u);
}
__device__ __forceinline__ float key2f(unsigned u) {
    unsigned b = (u & 0x80000000u) ? (u ^ 0x80000000u) : ~u;
    return __uint_as_float(b);
}
__device__ __forceinline__ void mma16816(float* d, const uint32_t* a,
                                         uint32_t b0, uint32_t b1) {
    asm volatile(
        "mma.sync.aligned.m16n8k16.row.col.f32.f16.f16.f32 "
        "{%0,%1,%2,%3}, {%4,%5,%6,%7}, {%8,%9}, {%0,%1,%2,%3};"
        : "+f"(d[0]), "+f"(d[1]), "+f"(d[2]), "+f"(d[3])
        : "r"(a[0]), "r"(a[1]), "r"(a[2]), "r"(a[3]), "r"(b0), "r"(b1));
}
__device__ __forceinline__ void ldsm4(uint32_t* r, const __half* p) {
    uint32_t a = (uint32_t)__cvta_generic_to_shared(p);
    asm volatile("ldmatrix.sync.aligned.m8n8.x4.shared.b16 {%0,%1,%2,%3}, [%4];"
                 : "=r"(r[0]), "=r"(r[1]), "=r"(r[2]), "=r"(r[3]) : "r"(a));
}

// ---------------- fp16 tensor-core GEMM, fused epilogues ----------------
// C[M,N] = sum of A_ta @ B_tb^T (skipping ta=1&tb=1 term).
// MODE 0: fp32 C + bias (inF0), ldc=ldx.
// MODE 1: fused AFT y: acc pairs (num,den); y=sigmoid(q)*(num+bs)/(den+bs) -> fp16 Y.
//         inF0 = dense q [row*128+d], inF1 = base.
// MODE 2: fused masked max -> atomicMax outU (inI=mask, ldx=SEQ).
// MODE 3: fused projection epilogue (ldx=SEQ). bcol<256: cols are (k_d,v_d) pairs;
//         compute e=mask*exp(k+bk), ev=e*(v+bv); atomicAdd fp32 col-sums to outB;
//         smem-transpose and write fp16 KV (outH). bcol==256: q part -> dense fp32
//         outF[row*128+qd] + bias.
// Tile 128x128x32, 256 threads, 8 warps (4m x 2n), warp tile 32x64.
// smem: row r, 16B chunk c -> phys chunk = c ^ ((r>>1)&3). Dynamic smem.
template <int TA, int TB, int MODE>
__global__ __launch_bounds__(256, 1) void gemm_hf(
    const __half* __restrict__ A0, const __half* __restrict__ A1,
    const __half* __restrict__ B0, const __half* __restrict__ B1,
    const float* __restrict__ inF0, const float* __restrict__ inF1,
    const int* __restrict__ inI,
    float* __restrict__ outF, __half* __restrict__ outH,
    unsigned* __restrict__ outU, float* __restrict__ outB,
    int K, int lda, int ldb, int ldx)
{
    extern __shared__ __align__(16) __half dsm[];
    __half* sA0 = dsm;
    __half* sA1 = dsm + (TA - 1) * 4096;
    __half* sB0 = dsm + TA * 4096;
    __half* sB1 = dsm + (TA + TB - 1) * 4096;

    const int tid  = threadIdx.x;
    const int lane = tid & 31;
    const int wid  = tid >> 5;
    const int wm   = (wid >> 1) * 32;
    const int wn   = (wid & 1) * 64;
    const int brow = blockIdx.y * 128;
    const int bcol = blockIdx.x * 128;

    const int lr  = tid >> 2;
    const int lc  = tid & 3;
    const int so0 = lr * 32 + ((lc ^ ((lr >> 1) & 3)) * 8);
    const int so1 = (lr + 64) * 32 + ((lc ^ (((lr + 64) >> 1) & 3)) * 8);

    const __half* gA0 = A0 + (size_t)(brow + lr) * lda + lc * 8;
    const __half* gA1 = (TA > 1) ? (A1 + (size_t)(brow + lr) * lda + lc * 8) : A0;
    const __half* gB0 = B0 + (size_t)(bcol + lr) * ldb + lc * 8;
    const __half* gB1 = (TB > 1) ? (B1 + (size_t)(bcol + lr) * ldb + lc * 8) : B0;
    const size_t a64 = (size_t)64 * lda, b64 = (size_t)64 * ldb;

    uint4 ra0[2], ra1[2], rb0[2], rb1[2];
    ra0[0] = *(const uint4*)(gA0); ra0[1] = *(const uint4*)(gA0 + a64);
    if (TA > 1) { ra1[0] = *(const uint4*)(gA1); ra1[1] = *(const uint4*)(gA1 + a64); }
    rb0[0] = *(const uint4*)(gB0); rb0[1] = *(const uint4*)(gB0 + b64);
    if (TB > 1) { rb1[0] = *(const uint4*)(gB1); rb1[1] = *(const uint4*)(gB1 + b64); }

    float acc[2][8][4] = {};

    const int arow_b = (lane & 7) + ((lane >> 3) & 1) * 8;
    const int achk_b = (lane >> 4);
    const int brow_b = (lane & 7) + (lane >> 4) * 8;
    const int bchk_b = (lane >> 3) & 1;

    for (int k0 = 0; k0 < K; k0 += 32) {
        *(uint4*)&sA0[so0] = ra0[0]; *(uint4*)&sA0[so1] = ra0[1];
        if (TA > 1) { *(uint4*)&sA1[so0] = ra1[0]; *(uint4*)&sA1[so1] = ra1[1]; }
        *(uint4*)&sB0[so0] = rb0[0]; *(uint4*)&sB0[so1] = rb0[1];
        if (TB > 1) { *(uint4*)&sB1[so0] = rb1[0]; *(uint4*)&sB1[so1] = rb1[1]; }
        __syncthreads();

        if (k0 + 32 < K) {
            ra0[0] = *(const uint4*)(gA0 + k0 + 32);
            ra0[1] = *(const uint4*)(gA0 + a64 + k0 + 32);
            if (TA > 1) {
                ra1[0] = *(const uint4*)(gA1 + k0 + 32);
                ra1[1] = *(const uint4*)(gA1 + a64 + k0 + 32);
            }
            rb0[0] = *(const uint4*)(gB0 + k0 + 32);
            rb0[1] = *(const uint4*)(gB0 + b64 + k0 + 32);
            if (TB > 1) {
                rb1[0] = *(const uint4*)(gB1 + k0 + 32);
                rb1[1] = *(const uint4*)(gB1 + b64 + k0 + 32);
            }
        }

        #pragma unroll
        for (int ck = 0; ck < 2; ck++) {
            uint32_t af[TA][2][4];
            #pragma unroll
            for (int mt = 0; mt < 2; mt++) {
                int row = wm + mt * 16 + arow_b;
                int chk = 2 * ck + achk_b;
                int off = row * 32 + ((chk ^ ((row >> 1) & 3)) * 8);
                ldsm4(af[0][mt], &sA0[off]);
                if (TA > 1) ldsm4(af[TA - 1][mt], &sA1[off]);
            }
            #pragma unroll
            for (int ntp = 0; ntp < 4; ntp++) {
                int row = wn + ntp * 16 + brow_b;
                int chk = 2 * ck + bchk_b;
                int off = row * 32 + ((chk ^ ((row >> 1) & 3)) * 8);
                uint32_t bf0[4], bf1[4];
                ldsm4(bf0, &sB0[off]);
                if (TB > 1) ldsm4(bf1, &sB1[off]);
                #pragma unroll
                for (int mt = 0; mt < 2; mt++) {
                    mma16816(acc[mt][2 * ntp],     af[0][mt], bf0[0], bf0[1]);
                    mma16816(acc[mt][2 * ntp + 1], af[0][mt], bf0[2], bf0[3]);
                    if (TB > 1) {
                        mma16816(acc[mt][2 * ntp],     af[0][mt], bf1[0], bf1[1]);
                        mma16816(acc[mt][2 * ntp + 1], af[0][mt], bf1[2], bf1[3]);
                    }
                    if (TA > 1) {
                        mma16816(acc[mt][2 * ntp],     af[TA - 1][mt], bf0[0], bf0[1]);
                        mma16816(acc[mt][2 * ntp + 1], af[TA - 1][mt], bf0[2], bf0[3]);
                    }
                }
            }
        }
        __syncthreads();
    }

    const int g = lane >> 2;
    const int c = lane & 3;

    if (MODE == 0) {
        #pragma unroll
        for (int mt = 0; mt < 2; mt++) {
            #pragma unroll
            for (int nt = 0; nt < 8; nt++) {
                int row = brow + wm + mt * 16 + g;
                int col = bcol + wn + nt * 8 + 2 * c;
                float bx = inF0[col], by = inF0[col + 1];
                float2 v0, v1;
                v0.x = acc[mt][nt][0] + bx; v0.y = acc[mt][nt][1] + by;
                v1.x = acc[mt][nt][2] + bx; v1.y = acc[mt][nt][3] + by;
                *(float2*)&outF[(size_t)row * ldx + col]       = v0;
                *(float2*)&outF[(size_t)(row + 8) * ldx + col] = v1;
            }
        }
    } else if (MODE == 1) {
        const int M = gridDim.y * 128;
        const int b = bcol >> 8;
        #pragma unroll
        for (int mt = 0; mt < 2; mt++) {
            #pragma unroll
            for (int nt = 0; nt < 8; nt++) {
                int row = brow + wm + mt * 16 + g;
                int col = bcol + wn + nt * 8 + 2 * c;
                int d = (col & 255) >> 1;
                float2 bs = *(const float2*)&inF1[col];
                #pragma unroll
                for (int r2 = 0; r2 < 2; r2++) {
                    int rr = row + 8 * r2;
                    float num = acc[mt][nt][2 * r2]     + bs.x;
                    float den = acc[mt][nt][2 * r2 + 1] + bs.y;
                    float q = inF0[((size_t)b * M + rr) * 128 + d];
                    float sg = 1.f / (1.f + expf(-q));
                    float y = sg * num / den;
                    outH[((size_t)b * M + rr) * 128 + d] = __float2half(y);
                }
            }
        }
    } else if (MODE == 2) {
        const int SEQ = ldx;
        const int b = brow / SEQ;
        int msk[2][2];
        #pragma unroll
        for (int mt = 0; mt < 2; mt++) {
            msk[mt][0] = inI[brow + wm + mt * 16 + g];
            msk[mt][1] = inI[brow + wm + mt * 16 + g + 8];
        }
        #pragma unroll
        for (int nt = 0; nt < 8; nt++) {
            float m0 = -3.0e38f, m1 = -3.0e38f;
            #pragma unroll
            for (int mt = 0; mt < 2; mt++) {
                if (msk[mt][0]) { m0 = fmaxf(m0, acc[mt][nt][0]); m1 = fmaxf(m1, acc[mt][nt][1]); }
                if (msk[mt][1]) { m0 = fmaxf(m0, acc[mt][nt][2]); m1 = fmaxf(m1, acc[mt][nt][3]); }
            }
            #pragma unroll
            for (int off = 4; off < 32; off <<= 1) {
                m0 = fmaxf(m0, __shfl_xor_sync(0xffffffffu, m0, off));
                m1 = fmaxf(m1, __shfl_xor_sync(0xffffffffu, m1, off));
            }
            if (g == 0) {
                int col = wn + nt * 8 + 2 * c;
                if (m0 > -2.9e38f) atomicMax(&outU[b * 128 + col],     f2key(m0));
                if (m1 > -2.9e38f) atomicMax(&outU[b * 128 + col + 1], f2key(m1));
            }
        }
    } else {
        // MODE 3: fused projection epilogue
        const int SEQ = ldx;
        const int b   = brow / SEQ;
        const int j0  = brow - b * SEQ;
        __half* st = dsm;   // [128][136] transpose buffer (overlaps SA/SB)
        if (bcol < 256) {
            __syncthreads();   // SA/SB done; reuse smem as st
            int msk[2][2];
            #pragma unroll
            for (int mt = 0; mt < 2; mt++) {
                msk[mt][0] = inI[brow + wm + mt * 16 + g];
                msk[mt][1] = inI[brow + wm + mt * 16 + g + 8];
            }
            #pragma unroll
            for (int nt = 0; nt < 8; nt++) {
                int colp = wn + nt * 8 + 2 * c;   // local even col (k)
                int dl   = colp >> 1;             // 0..63
                float bk = inF0[bcol + colp];
                float bv = inF0[bcol + colp + 1];
                float sev = 0.f, se = 0.f;
                #pragma unroll
                for (int mt = 0; mt < 2; mt++) {
                    #pragma unroll
                    for (int r2 = 0; r2 < 2; r2++) {
                        int rowl = wm + mt * 16 + g + 8 * r2;
                        float kk = acc[mt][nt][2 * r2]     + bk;
                        float vv = acc[mt][nt][2 * r2 + 1] + bv;
                        float e  = msk[mt][r2] ? expf(kk) : 0.f;
                        float ev = e * vv;
                        sev += ev; se += e;
                        st[(2 * dl)     * 136 + rowl] = __float2half(ev);
                        st[(2 * dl + 1) * 136 + rowl] = __float2half(e);
                    }
                }
                sev += __shfl_xor_sync(0xffffffffu, sev, 4);
                se  += __shfl_xor_sync(0xffffffffu, se, 4);
                sev += __shfl_xor_sync(0xffffffffu, sev, 8);
                se  += __shfl_xor_sync(0xffffffffu, se, 8);
                sev += __shfl_xor_sync(0xffffffffu, sev, 16);
                se  += __shfl_xor_sync(0xffffffffu, se, 16);
                if (g == 0) {
                    atomicAdd(&outB[b * 256 + bcol + 2 * dl],     sev);
                    atomicAdd(&outB[b * 256 + bcol + 2 * dl + 1], se);
                }
            }
            __syncthreads();
            // coalesced KV writeout: thread covers 64 contiguous j's of one row
            int rl = tid >> 1, jh = (tid & 1) * 64;
            const __half* src = &st[rl * 136 + jh];
            __half* dst = outH + ((size_t)(b * 256 + bcol + rl)) * SEQ + j0 + jh;
            #pragma unroll
            for (int u = 0; u < 8; u++)
                *(uint4*)(dst + 8 * u) = *(const uint4*)(src + 8 * u);
        } else {
            // q part -> dense fp32 [row*128 + qd]
            #pragma unroll
            for (int mt = 0; mt < 2; mt++) {
                #pragma unroll
                for (int nt = 0; nt < 8; nt++) {
                    int colp = wn + nt * 8 + 2 * c;
                    float bx = inF0[256 + colp], by = inF0[256 + colp + 1];
                    int row = brow + wm + mt * 16 + g;
                    float2 v0, v1;
                    v0.x = acc[mt][nt][0] + bx; v0.y = acc[mt][nt][1] + by;
                    v1.x = acc[mt][nt][2] + bx; v1.y = acc[mt][nt][3] + by;
                    *(float2*)&outF[(size_t)row * 128 + colp]       = v0;
                    *(float2*)&outF[(size_t)(row + 8) * 128 + colp] = v1;
                }
            }
        }
    }
}

// ---------------- small kernels ----------------
__global__ void k_init(unsigned* ob1, unsigned* ob2, float* base1, float* base2) {
    int i = blockIdx.x * 256 + threadIdx.x;
    if (i < Bn * 128) {
        unsigned k = f2key(NEGV);
        ob1[i] = k; ob2[i] = k;
    }
    if (i < NB) { base1[i] = 0.f; base2[i] = 0.f; }
}

__global__ void k_expf(const float* __restrict__ pb, __half* __restrict__ F1,
                       __half* __restrict__ F2) {
    __shared__ float s[32][33];
    int j0 = blockIdx.x * 32, i0 = blockIdx.y * 32;
    int tx = threadIdx.x & 31, ty = threadIdx.x >> 5;
    #pragma unroll
    for (int r = ty; r < 32; r += 8) {
        float v = expf(pb[(i0 + r) * 1024 + j0 + tx]) - 1.0f;
        F1[(i0 + r) * Tp + j0 + tx] = __float2half(v);
        s[r][tx] = v;
    }
    __syncthreads();
    #pragma unroll
    for (int r = ty; r < 32; r += 8)
        F2[(j0 + r) * Td + i0 + tx] = __float2half(s[tx][r]);
}

// fp32 -> fp16 convert; 8 floats per thread, 16B stores
__global__ void k_half(const float* __restrict__ x, __half* __restrict__ h, int n8) {
    int i = blockIdx.x * 256 + threadIdx.x;
    if (i >= n8) return;
    float4 v0 = ((const float4*)x)[2 * i];
    float4 v1 = ((const float4*)x)[2 * i + 1];
    uint32_t hh[4];
    __half2 p;
    p = __floats2half2_rn(v0.x, v0.y); hh[0] = *(uint32_t*)&p;
    p = __floats2half2_rn(v0.z, v0.w); hh[1] = *(uint32_t*)&p;
    p = __floats2half2_rn(v1.x, v1.y); hh[2] = *(uint32_t*)&p;
    p = __floats2half2_rn(v1.z, v1.w); hh[3] = *(uint32_t*)&p;
    ((uint4*)h)[i] = make_uint4(hh[0], hh[1], hh[2], hh[3]);
}

// fp32 -> (hi, lo) fp16 split
__global__ void k_split(const float* __restrict__ x, __half* __restrict__ h,
                        __half* __restrict__ l, int n) {
    int i = blockIdx.x * 256 + threadIdx.x;
    if (i >= n) return;
    float w = x[i];
    __half hi = __float2half(w);
    h[i] = hi;
    l[i] = __float2half(w - __half2float(hi));
}

// pack W rows interleaved: r<256: even=k[r/2], odd=v[r/2]; r>=256: q[r-256]
__global__ void k_pack_split(const float* __restrict__ Wk, const float* __restrict__ bk,
                             const float* __restrict__ Wv, const float* __restrict__ bv,
                             const float* __restrict__ Wq, const float* __restrict__ bq,
                             __half* __restrict__ Wh, __half* __restrict__ Wl,
                             float* __restrict__ bp) {
    int i = blockIdx.x * 256 + threadIdx.x;
    if (i < 384 * 128) {
        int r = i >> 7, cc = i & 127;
        const float* s;
        int sr;
        if (r < 256) { s = (r & 1) ? Wv : Wk; sr = r >> 1; }
        else         { s = Wq; sr = r - 256; }
        float w = s[sr * 128 + cc];
        __half h = __float2half(w);
        Wh[i] = h;
        Wl[i] = __float2half(w - __half2float(h));
    }
    if (i < 384) {
        bp[i] = (i < 256) ? ((i & 1) ? bv[i >> 1] : bk[i >> 1]) : bq[i - 256];
    }
}

__global__ void k_out(const unsigned* __restrict__ ob1, const unsigned* __restrict__ ob2,
                      const float* __restrict__ bpd, const float* __restrict__ bpp,
                      float* __restrict__ out) {
    int i = blockIdx.x * 256 + threadIdx.x;
    if (i < Bn * 128) {
        int t = i & 127;
        out[i]            = key2f(ob1[i]) + bpd[t];
        out[Bn * 128 + i] = key2f(ob2[i]) + bpp[t];
    }
}

// ---------------- launch ----------------
#define SYM(p, s) cudaGetSymbolAddress((void**)&p, s)
#define NUL_F (const float*)0
#define NUL_I (const int*)0
#define NUL_H (const __half*)0

extern "C" void kernel_launch(void* const* d_in, const int* in_sizes, int n_in,
                              void* d_out, int out_size) {
    const float* smiles  = (const float*)d_in[0];
    const float* protein = (const float*)d_in[1];
    const int*   smask   = (const int*)d_in[2];
    const int*   pmask   = (const int*)d_in[3];
    const float* pb      = (const float*)d_in[4];
    const float* Wqd = (const float*)d_in[5],  *bqd = (const float*)d_in[6];
    const float* Wkp = (const float*)d_in[7],  *bkp = (const float*)d_in[8];
    const float* Wvp = (const float*)d_in[9],  *bvp = (const float*)d_in[10];
    const float* Wqp = (const float*)d_in[11], *bqp = (const float*)d_in[12];
    const float* Wkd = (const float*)d_in[13], *bkd = (const float*)d_in[14];
    const float* Wvd = (const float*)d_in[15], *bvd = (const float*)d_in[16];
    const float* Wpd = (const float*)d_in[17], *bpd = (const float*)d_in[18];
    const float* Wpp = (const float*)d_in[19], *bpp = (const float*)d_in[20];
    float* out = (float*)d_out;

    __half *F1h, *F2h, *Xph, *Xsh, *Wp1h, *Wp1l, *Wp2h, *Wp2l;
    __half *Wodh, *Wodl, *Woph, *Wopl, *KV1th, *KV2th, *Y1h, *Y2h;
    float *bp1, *bp2, *Q1, *Q2, *base1, *base2;
    unsigned *ob1, *ob2;
    SYM(F1h, g_F1h);   SYM(F2h, g_F2h);
    SYM(Xph, g_Xph);   SYM(Xsh, g_Xsh);
    SYM(Wp1h, g_Wp1h); SYM(Wp1l, g_Wp1l); SYM(Wp2h, g_Wp2h); SYM(Wp2l, g_Wp2l);
    SYM(bp1, g_bp1);   SYM(bp2, g_bp2);
    SYM(Wodh, g_Wodh); SYM(Wodl, g_Wodl); SYM(Woph, g_Woph); SYM(Wopl, g_Wopl);
    SYM(Q1, g_Q1);     SYM(Q2, g_Q2);
    SYM(KV1th, g_KV1th); SYM(KV2th, g_KV2th);
    SYM(base1, g_base1); SYM(base2, g_base2);
    SYM(Y1h, g_Y1h);   SYM(Y2h, g_Y2h);
    SYM(ob1, g_ob1);   SYM(ob2, g_ob2);

    const int SM_PROJ = 136 * 128 * 2;       // 34816 (st overlaps 24KB loop region)
    const int SM_MAIN = 2 * 8192;            // TA=1,TB=1
    const int SM_OUT  = 3 * 8192;            // TA=1,TB=2

    // init + batch-independent precompute
    k_init<<<NB / 256, 256>>>(ob1, ob2, base1, base2);
    k_expf<<<dim3(Tp / 32, Td / 32), 256>>>(pb, F1h, F2h);
    k_half<<<(Bn * Tp * 128 / 8 + 255) / 256, 256>>>(protein, Xph, Bn * Tp * 128 / 8);
    k_half<<<(Bn * Td * 128 / 8 + 255) / 256, 256>>>(smiles, Xsh, Bn * Td * 128 / 8);
    k_split<<<(128 * 128 + 255) / 256, 256>>>(Wpd, Wodh, Wodl, 128 * 128);
    k_split<<<(128 * 128 + 255) / 256, 256>>>(Wpp, Woph, Wopl, 128 * 128);
    k_pack_split<<<192, 256>>>(Wkp, bkp, Wvp, bvp, Wqp, bqp, Wp1h, Wp1l, bp1);
    k_pack_split<<<192, 256>>>(Wkd, bkd, Wvd, bvd, Wqd, bqd, Wp2h, Wp2l, bp2);

    // fused projections + KV build + base sums + dense q  (MODE 3)
    gemm_hf<1, 2, 3><<<dim3(3, (Bn * Tp) / 128), 256, SM_PROJ>>>(
        Xph, NUL_H, Wp1h, Wp1l, bp1, NUL_F, pmask, Q1, KV1th, (unsigned*)0, base1,
        128, 128, 128, Tp);
    gemm_hf<1, 2, 3><<<dim3(3, (Bn * Td) / 128), 256, SM_PROJ>>>(
        Xsh, NUL_H, Wp2h, Wp2l, bp2, NUL_F, smask, Q2, KV2th, (unsigned*)0, base2,
        128, 128, 128, Td);

    // main AFT GEMMs (single product F @ KV) with fused y-epilogue
    gemm_hf<1, 1, 1><<<dim3(NB / 128, Td / 128), 256, SM_MAIN>>>(
        F1h, NUL_H, KV1th, NUL_H, Q2, base1, NUL_I, (float*)0, Y1h, (unsigned*)0,
        (float*)0, Tp, Tp, Tp, 0);
    gemm_hf<1, 1, 1><<<dim3(NB / 128, Tp / 128), 256, SM_MAIN>>>(
        F2h, NUL_H, KV2th, NUL_H, Q1, base2, NUL_I, (float*)0, Y2h, (unsigned*)0,
        (float*)0, Td, Td, Td, 0);

    // output projections (Y fp16 @ Wo hi/lo) with fused masked-max
    gemm_hf<1, 2, 2><<<dim3(1, (Bn * Td) / 128), 256, SM_OUT>>>(
        Y1h, NUL_H, Wodh, Wodl, NUL_F, NUL_F, smask, (float*)0, (__half*)0, ob1,
        (float*)0, 128, 128, 128, Td);
    gemm_hf<1, 2, 2><<<dim3(1, (Bn * Tp) / 128), 256, SM_OUT>>>(
        Y2h, NUL_H, Woph, Wopl, NUL_F, NUL_F, pmask, (float*)0, (__half*)0, ob2,
        (float*)0, 128, 128, 128, Tp);

    // decode + add output bias
    k_out<<<(Bn * 128 + 255) / 256, 256>>>(ob1, ob2, bpd, bpp, out);
}

// round 11
// speedup vs baseline: 1.7881x; 1.0952x over previous
#include <cuda_runtime.h>
#include <cuda_fp16.h>
#include <math.h>
#include <stdint.h>

// Problem constants
#define Bn   64
#define Td   256
#define Tp   1024
#define NB   (Bn * 256)
#define NEGV (-1e9f)
#define AL   __align__(256)

// ---------------- device scratch ----------------
__device__ AL __half g_F1h[Td * Tp];
__device__ AL __half g_F2h[Tp * Td];
__device__ AL __half g_Xph[Bn * Tp * 128];
__device__ AL __half g_Xsh[Bn * Td * 128];
__device__ AL __half g_Wp1h[384 * 128];     // rows: k0,v0,k1,v1,...,q0..q127
__device__ AL __half g_Wp2h[384 * 128];
__device__ AL float g_bp1[384], g_bp2[384];
__device__ AL __half g_Wodh[128 * 128];
__device__ AL __half g_Woph[128 * 128];
__device__ AL float g_Q1[Bn * Tp * 128];    // dense q projections
__device__ AL float g_Q2[Bn * Td * 128];
__device__ AL __half g_KV1th[NB * Tp];      // rows b*256+2d(ev)/2d+1(e), cols j
__device__ AL __half g_KV2th[NB * Td];
__device__ AL float g_base1[NB], g_base2[NB];   // interleaved [b*256 + 2d + {0,1}]
__device__ AL __half g_Y1h[Bn * Td * 128];
__device__ AL __half g_Y2h[Bn * Tp * 128];
__device__ AL unsigned g_ob1[Bn * 128], g_ob2[Bn * 128];

// ---------------- helpers ----------------
__device__ __forceinline__ unsigned f2key(float f) {
    unsigned u = __float_as_uint(f);
    return (u & 0x80000000u) ? ~u : (u | 0x80000000u);
}
__device__ __forceinline__ float key2f(unsigned u) {
    unsigned b = (u & 0x80000000u) ? (u ^ 0x80000000u) : ~u;
    return __uint_as_float(b);
}
__device__ __forceinline__ void mma16816(float* d, const uint32_t* a,
                                         uint32_t b0, uint32_t b1) {
    asm volatile(
        "mma.sync.aligned.m16n8k16.row.col.f32.f16.f16.f32 "
        "{%0,%1,%2,%3}, {%4,%5,%6,%7}, {%8,%9}, {%0,%1,%2,%3};"
        : "+f"(d[0]), "+f"(d[1]), "+f"(d[2]), "+f"(d[3])
        : "r"(a[0]), "r"(a[1]), "r"(a[2]), "r"(a[3]), "r"(b0), "r"(b1));
}
__device__ __forceinline__ void ldsm4(uint32_t* r, const __half* p) {
    uint32_t a = (uint32_t)__cvta_generic_to_shared(p);
    asm volatile("ldmatrix.sync.aligned.m8n8.x4.shared.b16 {%0,%1,%2,%3}, [%4];"
                 : "=r"(r[0]), "=r"(r[1]), "=r"(r[2]), "=r"(r[3]) : "r"(a));
}

// ---------------- fp16 tensor-core GEMM, fused epilogues ----------------
// C[M,N] = sum of A_ta @ B_tb^T (skipping ta=1&tb=1 term).
// MODE 0: fp32 C + bias (inF0), ldc=ldx.
// MODE 1: fused AFT y: acc pairs (num,den); y=sigmoid(q)*(num+bs)/(den+bs) -> fp16 Y.
//         inF0 = dense q [row*128+d], inF1 = base.
// MODE 2: fused masked max -> atomicMax outU (inI=mask, ldx=SEQ).
// MODE 3: fused projection epilogue (ldx=SEQ). bcol<256: cols are (k_d,v_d) pairs;
//         compute e=mask*exp(k+bk), ev=e*(v+bv); atomicAdd fp32 col-sums to outB;
//         smem-transpose and write fp16 KV (outH). bcol==256: q part -> dense fp32
//         outF[row*128+qd] + bias.
// Tile 128x128x32, 256 threads, 8 warps (4m x 2n), warp tile 32x64.
// smem: row r, 16B chunk c -> phys chunk = c ^ ((r>>1)&3). Dynamic smem.
template <int TA, int TB, int MODE>
__global__ __launch_bounds__(256, 1) void gemm_hf(
    const __half* __restrict__ A0, const __half* __restrict__ A1,
    const __half* __restrict__ B0, const __half* __restrict__ B1,
    const float* __restrict__ inF0, const float* __restrict__ inF1,
    const int* __restrict__ inI,
    float* __restrict__ outF, __half* __restrict__ outH,
    unsigned* __restrict__ outU, float* __restrict__ outB,
    int K, int lda, int ldb, int ldx)
{
    extern __shared__ __align__(16) __half dsm[];
    __half* sA0 = dsm;
    __half* sA1 = dsm + (TA - 1) * 4096;
    __half* sB0 = dsm + TA * 4096;
    __half* sB1 = dsm + (TA + TB - 1) * 4096;

    const int tid  = threadIdx.x;
    const int lane = tid & 31;
    const int wid  = tid >> 5;
    const int wm   = (wid >> 1) * 32;
    const int wn   = (wid & 1) * 64;
    const int brow = blockIdx.y * 128;
    const int bcol = blockIdx.x * 128;

    const int lr  = tid >> 2;
    const int lc  = tid & 3;
    const int so0 = lr * 32 + ((lc ^ ((lr >> 1) & 3)) * 8);
    const int so1 = (lr + 64) * 32 + ((lc ^ (((lr + 64) >> 1) & 3)) * 8);

    const __half* gA0 = A0 + (size_t)(brow + lr) * lda + lc * 8;
    const __half* gA1 = (TA > 1) ? (A1 + (size_t)(brow + lr) * lda + lc * 8) : A0;
    const __half* gB0 = B0 + (size_t)(bcol + lr) * ldb + lc * 8;
    const __half* gB1 = (TB > 1) ? (B1 + (size_t)(bcol + lr) * ldb + lc * 8) : B0;
    const size_t a64 = (size_t)64 * lda, b64 = (size_t)64 * ldb;

    uint4 ra0[2], ra1[2], rb0[2], rb1[2];
    ra0[0] = *(const uint4*)(gA0); ra0[1] = *(const uint4*)(gA0 + a64);
    if (TA > 1) { ra1[0] = *(const uint4*)(gA1); ra1[1] = *(const uint4*)(gA1 + a64); }
    rb0[0] = *(const uint4*)(gB0); rb0[1] = *(const uint4*)(gB0 + b64);
    if (TB > 1) { rb1[0] = *(const uint4*)(gB1); rb1[1] = *(const uint4*)(gB1 + b64); }

    float acc[2][8][4] = {};

    const int arow_b = (lane & 7) + ((lane >> 3) & 1) * 8;
    const int achk_b = (lane >> 4);
    const int brow_b = (lane & 7) + (lane >> 4) * 8;
    const int bchk_b = (lane >> 3) & 1;

    for (int k0 = 0; k0 < K; k0 += 32) {
        *(uint4*)&sA0[so0] = ra0[0]; *(uint4*)&sA0[so1] = ra0[1];
        if (TA > 1) { *(uint4*)&sA1[so0] = ra1[0]; *(uint4*)&sA1[so1] = ra1[1]; }
        *(uint4*)&sB0[so0] = rb0[0]; *(uint4*)&sB0[so1] = rb0[1];
        if (TB > 1) { *(uint4*)&sB1[so0] = rb1[0]; *(uint4*)&sB1[so1] = rb1[1]; }
        __syncthreads();

        if (k0 + 32 < K) {
            ra0[0] = *(const uint4*)(gA0 + k0 + 32);
            ra0[1] = *(const uint4*)(gA0 + a64 + k0 + 32);
            if (TA > 1) {
                ra1[0] = *(const uint4*)(gA1 + k0 + 32);
                ra1[1] = *(const uint4*)(gA1 + a64 + k0 + 32);
            }
            rb0[0] = *(const uint4*)(gB0 + k0 + 32);
            rb0[1] = *(const uint4*)(gB0 + b64 + k0 + 32);
            if (TB > 1) {
                rb1[0] = *(const uint4*)(gB1 + k0 + 32);
                rb1[1] = *(const uint4*)(gB1 + b64 + k0 + 32);
            }
        }

        #pragma unroll
        for (int ck = 0; ck < 2; ck++) {
            uint32_t af[TA][2][4];
            #pragma unroll
            for (int mt = 0; mt < 2; mt++) {
                int row = wm + mt * 16 + arow_b;
                int chk = 2 * ck + achk_b;
                int off = row * 32 + ((chk ^ ((row >> 1) & 3)) * 8);
                ldsm4(af[0][mt], &sA0[off]);
                if (TA > 1) ldsm4(af[TA - 1][mt], &sA1[off]);
            }
            #pragma unroll
            for (int ntp = 0; ntp < 4; ntp++) {
                int row = wn + ntp * 16 + brow_b;
                int chk = 2 * ck + bchk_b;
                int off = row * 32 + ((chk ^ ((row >> 1) & 3)) * 8);
                uint32_t bf0[4], bf1[4];
                ldsm4(bf0, &sB0[off]);
                if (TB > 1) ldsm4(bf1, &sB1[off]);
                #pragma unroll
                for (int mt = 0; mt < 2; mt++) {
                    mma16816(acc[mt][2 * ntp],     af[0][mt], bf0[0], bf0[1]);
                    mma16816(acc[mt][2 * ntp + 1], af[0][mt], bf0[2], bf0[3]);
                    if (TB > 1) {
                        mma16816(acc[mt][2 * ntp],     af[0][mt], bf1[0], bf1[1]);
                        mma16816(acc[mt][2 * ntp + 1], af[0][mt], bf1[2], bf1[3]);
                    }
                    if (TA > 1) {
                        mma16816(acc[mt][2 * ntp],     af[TA - 1][mt], bf0[0], bf0[1]);
                        mma16816(acc[mt][2 * ntp + 1], af[TA - 1][mt], bf0[2], bf0[3]);
                    }
                }
            }
        }
        __syncthreads();
    }

    const int g = lane >> 2;
    const int c = lane & 3;

    if (MODE == 0) {
        #pragma unroll
        for (int mt = 0; mt < 2; mt++) {
            #pragma unroll
            for (int nt = 0; nt < 8; nt++) {
                int row = brow + wm + mt * 16 + g;
                int col = bcol + wn + nt * 8 + 2 * c;
                float bx = inF0[col], by = inF0[col + 1];
                float2 v0, v1;
                v0.x = acc[mt][nt][0] + bx; v0.y = acc[mt][nt][1] + by;
                v1.x = acc[mt][nt][2] + bx; v1.y = acc[mt][nt][3] + by;
                *(float2*)&outF[(size_t)row * ldx + col]       = v0;
                *(float2*)&outF[(size_t)(row + 8) * ldx + col] = v1;
            }
        }
    } else if (MODE == 1) {
        const int M = gridDim.y * 128;
        const int b = bcol >> 8;
        #pragma unroll
        for (int mt = 0; mt < 2; mt++) {
            #pragma unroll
            for (int nt = 0; nt < 8; nt++) {
                int row = brow + wm + mt * 16 + g;
                int col = bcol + wn + nt * 8 + 2 * c;
                int d = (col & 255) >> 1;
                float2 bs = *(const float2*)&inF1[col];
                #pragma unroll
                for (int r2 = 0; r2 < 2; r2++) {
                    int rr = row + 8 * r2;
                    float num = acc[mt][nt][2 * r2]     + bs.x;
                    float den = acc[mt][nt][2 * r2 + 1] + bs.y;
                    float q = inF0[((size_t)b * M + rr) * 128 + d];
                    float sg = 1.f / (1.f + expf(-q));
                    float y = sg * num / den;
                    outH[((size_t)b * M + rr) * 128 + d] = __float2half(y);
                }
            }
        }
    } else if (MODE == 2) {
        const int SEQ = ldx;
        const int b = brow / SEQ;
        int msk[2][2];
        #pragma unroll
        for (int mt = 0; mt < 2; mt++) {
            msk[mt][0] = inI[brow + wm + mt * 16 + g];
            msk[mt][1] = inI[brow + wm + mt * 16 + g + 8];
        }
        #pragma unroll
        for (int nt = 0; nt < 8; nt++) {
            float m0 = -3.0e38f, m1 = -3.0e38f;
            #pragma unroll
            for (int mt = 0; mt < 2; mt++) {
                if (msk[mt][0]) { m0 = fmaxf(m0, acc[mt][nt][0]); m1 = fmaxf(m1, acc[mt][nt][1]); }
                if (msk[mt][1]) { m0 = fmaxf(m0, acc[mt][nt][2]); m1 = fmaxf(m1, acc[mt][nt][3]); }
            }
            #pragma unroll
            for (int off = 4; off < 32; off <<= 1) {
                m0 = fmaxf(m0, __shfl_xor_sync(0xffffffffu, m0, off));
                m1 = fmaxf(m1, __shfl_xor_sync(0xffffffffu, m1, off));
            }
            if (g == 0) {
                int col = wn + nt * 8 + 2 * c;
                if (m0 > -2.9e38f) atomicMax(&outU[b * 128 + col],     f2key(m0));
                if (m1 > -2.9e38f) atomicMax(&outU[b * 128 + col + 1], f2key(m1));
            }
        }
    } else {
        // MODE 3: fused projection epilogue
        const int SEQ = ldx;
        const int b   = brow / SEQ;
        const int j0  = brow - b * SEQ;
        __half* st = dsm;   // [128][136] transpose buffer (overlaps SA/SB)
        if (bcol < 256) {
            __syncthreads();   // SA/SB done; reuse smem as st
            int msk[2][2];
            #pragma unroll
            for (int mt = 0; mt < 2; mt++) {
                msk[mt][0] = inI[brow + wm + mt * 16 + g];
                msk[mt][1] = inI[brow + wm + mt * 16 + g + 8];
            }
            #pragma unroll
            for (int nt = 0; nt < 8; nt++) {
                int colp = wn + nt * 8 + 2 * c;   // local even col (k)
                int dl   = colp >> 1;             // 0..63
                float bk = inF0[bcol + colp];
                float bv = inF0[bcol + colp + 1];
                float sev = 0.f, se = 0.f;
                #pragma unroll
                for (int mt = 0; mt < 2; mt++) {
                    #pragma unroll
                    for (int r2 = 0; r2 < 2; r2++) {
                        int rowl = wm + mt * 16 + g + 8 * r2;
                        float kk = acc[mt][nt][2 * r2]     + bk;
                        float vv = acc[mt][nt][2 * r2 + 1] + bv;
                        float e  = msk[mt][r2] ? expf(kk) : 0.f;
                        float ev = e * vv;
                        sev += ev; se += e;
                        st[(2 * dl)     * 136 + rowl] = __float2half(ev);
                        st[(2 * dl + 1) * 136 + rowl] = __float2half(e);
                    }
                }
                sev += __shfl_xor_sync(0xffffffffu, sev, 4);
                se  += __shfl_xor_sync(0xffffffffu, se, 4);
                sev += __shfl_xor_sync(0xffffffffu, sev, 8);
                se  += __shfl_xor_sync(0xffffffffu, se, 8);
                sev += __shfl_xor_sync(0xffffffffu, sev, 16);
                se  += __shfl_xor_sync(0xffffffffu, se, 16);
                if (g == 0) {
                    atomicAdd(&outB[b * 256 + bcol + 2 * dl],     sev);
                    atomicAdd(&outB[b * 256 + bcol + 2 * dl + 1], se);
                }
            }
            __syncthreads();
            // coalesced KV writeout: thread covers 64 contiguous j's of one row
            int rl = tid >> 1, jh = (tid & 1) * 64;
            const __half* src = &st[rl * 136 + jh];
            __half* dst = outH + ((size_t)(b * 256 + bcol + rl)) * SEQ + j0 + jh;
            #pragma unroll
            for (int u = 0; u < 8; u++)
                *(uint4*)(dst + 8 * u) = *(const uint4*)(src + 8 * u);
        } else {
            // q part -> dense fp32 [row*128 + qd]
            #pragma unroll
            for (int mt = 0; mt < 2; mt++) {
                #pragma unroll
                for (int nt = 0; nt < 8; nt++) {
                    int colp = wn + nt * 8 + 2 * c;
                    float bx = inF0[256 + colp], by = inF0[256 + colp + 1];
                    int row = brow + wm + mt * 16 + g;
                    float2 v0, v1;
                    v0.x = acc[mt][nt][0] + bx; v0.y = acc[mt][nt][1] + by;
                    v1.x = acc[mt][nt][2] + bx; v1.y = acc[mt][nt][3] + by;
                    *(float2*)&outF[(size_t)row * 128 + colp]       = v0;
                    *(float2*)&outF[(size_t)(row + 8) * 128 + colp] = v1;
                }
            }
        }
    }
}

// ---------------- small kernels ----------------
__global__ void k_init(unsigned* ob1, unsigned* ob2, float* base1, float* base2) {
    int i = blockIdx.x * 256 + threadIdx.x;
    if (i < Bn * 128) {
        unsigned k = f2key(NEGV);
        ob1[i] = k; ob2[i] = k;
    }
    if (i < NB) { base1[i] = 0.f; base2[i] = 0.f; }
}

__global__ void k_expf(const float* __restrict__ pb, __half* __restrict__ F1,
                       __half* __restrict__ F2) {
    __shared__ float s[32][33];
    int j0 = blockIdx.x * 32, i0 = blockIdx.y * 32;
    int tx = threadIdx.x & 31, ty = threadIdx.x >> 5;
    #pragma unroll
    for (int r = ty; r < 32; r += 8) {
        float v = expf(pb[(i0 + r) * 1024 + j0 + tx]) - 1.0f;
        F1[(i0 + r) * Tp + j0 + tx] = __float2half(v);
        s[r][tx] = v;
    }
    __syncthreads();
    #pragma unroll
    for (int r = ty; r < 32; r += 8)
        F2[(j0 + r) * Td + i0 + tx] = __float2half(s[tx][r]);
}

// fp32 -> fp16 convert; 8 floats per thread, 16B stores
__global__ void k_half(const float* __restrict__ x, __half* __restrict__ h, int n8) {
    int i = blockIdx.x * 256 + threadIdx.x;
    if (i >= n8) return;
    float4 v0 = ((const float4*)x)[2 * i];
    float4 v1 = ((const float4*)x)[2 * i + 1];
    uint32_t hh[4];
    __half2 p;
    p = __floats2half2_rn(v0.x, v0.y); hh[0] = *(uint32_t*)&p;
    p = __floats2half2_rn(v0.z, v0.w); hh[1] = *(uint32_t*)&p;
    p = __floats2half2_rn(v1.x, v1.y); hh[2] = *(uint32_t*)&p;
    p = __floats2half2_rn(v1.z, v1.w); hh[3] = *(uint32_t*)&p;
    ((uint4*)h)[i] = make_uint4(hh[0], hh[1], hh[2], hh[3]);
}

// pack W rows interleaved fp16: r<256: even=k[r/2], odd=v[r/2]; r>=256: q[r-256]
__global__ void k_pack_half(const float* __restrict__ Wk, const float* __restrict__ bk,
                            const float* __restrict__ Wv, const float* __restrict__ bv,
                            const float* __restrict__ Wq, const float* __restrict__ bq,
                            __half* __restrict__ Wh, float* __restrict__ bp) {
    int i = blockIdx.x * 256 + threadIdx.x;
    if (i < 384 * 128) {
        int r = i >> 7, cc = i & 127;
        const float* s;
        int sr;
        if (r < 256) { s = (r & 1) ? Wv : Wk; sr = r >> 1; }
        else         { s = Wq; sr = r - 256; }
        Wh[i] = __float2half(s[sr * 128 + cc]);
    }
    if (i < 384) {
        bp[i] = (i < 256) ? ((i & 1) ? bv[i >> 1] : bk[i >> 1]) : bq[i - 256];
    }
}

__global__ void k_out(const unsigned* __restrict__ ob1, const unsigned* __restrict__ ob2,
                      const float* __restrict__ bpd, const float* __restrict__ bpp,
                      float* __restrict__ out) {
    int i = blockIdx.x * 256 + threadIdx.x;
    if (i < Bn * 128) {
        int t = i & 127;
        out[i]            = key2f(ob1[i]) + bpd[t];
        out[Bn * 128 + i] = key2f(ob2[i]) + bpp[t];
    }
}

// ---------------- launch ----------------
#define SYM(p, s) cudaGetSymbolAddress((void**)&p, s)
#define NUL_F (const float*)0
#define NUL_I (const int*)0
#define NUL_H (const __half*)0

extern "C" void kernel_launch(void* const* d_in, const int* in_sizes, int n_in,
                              void* d_out, int out_size) {
    const float* smiles  = (const float*)d_in[0];
    const float* protein = (const float*)d_in[1];
    const int*   smask   = (const int*)d_in[2];
    const int*   pmask   = (const int*)d_in[3];
    const float* pb      = (const float*)d_in[4];
    const float* Wqd = (const float*)d_in[5],  *bqd = (const float*)d_in[6];
    const float* Wkp = (const float*)d_in[7],  *bkp = (const float*)d_in[8];
    const float* Wvp = (const float*)d_in[9],  *bvp = (const float*)d_in[10];
    const float* Wqp = (const float*)d_in[11], *bqp = (const float*)d_in[12];
    const float* Wkd = (const float*)d_in[13], *bkd = (const float*)d_in[14];
    const float* Wvd = (const float*)d_in[15], *bvd = (const float*)d_in[16];
    const float* Wpd = (const float*)d_in[17], *bpd = (const float*)d_in[18];
    const float* Wpp = (const float*)d_in[19], *bpp = (const float*)d_in[20];
    float* out = (float*)d_out;

    __half *F1h, *F2h, *Xph, *Xsh, *Wp1h, *Wp2h;
    __half *Wodh, *Woph, *KV1th, *KV2th, *Y1h, *Y2h;
    float *bp1, *bp2, *Q1, *Q2, *base1, *base2;
    unsigned *ob1, *ob2;
    SYM(F1h, g_F1h);   SYM(F2h, g_F2h);
    SYM(Xph, g_Xph);   SYM(Xsh, g_Xsh);
    SYM(Wp1h, g_Wp1h); SYM(Wp2h, g_Wp2h);
    SYM(bp1, g_bp1);   SYM(bp2, g_bp2);
    SYM(Wodh, g_Wodh); SYM(Woph, g_Woph);
    SYM(Q1, g_Q1);     SYM(Q2, g_Q2);
    SYM(KV1th, g_KV1th); SYM(KV2th, g_KV2th);
    SYM(base1, g_base1); SYM(base2, g_base2);
    SYM(Y1h, g_Y1h);   SYM(Y2h, g_Y2h);
    SYM(ob1, g_ob1);   SYM(ob2, g_ob2);

    const int SM_PROJ = 136 * 128 * 2;       // 34816 (st buffer; loop uses 16KB)
    const int SM_MAIN = 2 * 8192;            // TA=1,TB=1
    const int SM_OUT  = 2 * 8192;            // TA=1,TB=1

    // init + batch-independent precompute
    k_init<<<NB / 256, 256>>>(ob1, ob2, base1, base2);
    k_expf<<<dim3(Tp / 32, Td / 32), 256>>>(pb, F1h, F2h);
    k_half<<<(Bn * Tp * 128 / 8 + 255) / 256, 256>>>(protein, Xph, Bn * Tp * 128 / 8);
    k_half<<<(Bn * Td * 128 / 8 + 255) / 256, 256>>>(smiles, Xsh, Bn * Td * 128 / 8);
    k_half<<<(128 * 128 / 8 + 255) / 256, 256>>>(Wpd, Wodh, 128 * 128 / 8);
    k_half<<<(128 * 128 / 8 + 255) / 256, 256>>>(Wpp, Woph, 128 * 128 / 8);
    k_pack_half<<<192, 256>>>(Wkp, bkp, Wvp, bvp, Wqp, bqp, Wp1h, bp1);
    k_pack_half<<<192, 256>>>(Wkd, bkd, Wvd, bvd, Wqd, bqd, Wp2h, bp2);

    // fused projections + KV build + base sums + dense q  (MODE 3, single product)
    gemm_hf<1, 1, 3><<<dim3(3, (Bn * Tp) / 128), 256, SM_PROJ>>>(
        Xph, NUL_H, Wp1h, NUL_H, bp1, NUL_F, pmask, Q1, KV1th, (unsigned*)0, base1,
        128, 128, 128, Tp);
    gemm_hf<1, 1, 3><<<dim3(3, (Bn * Td) / 128), 256, SM_PROJ>>>(
        Xsh, NUL_H, Wp2h, NUL_H, bp2, NUL_F, smask, Q2, KV2th, (unsigned*)0, base2,
        128, 128, 128, Td);

    // main AFT GEMMs (single product F @ KV) with fused y-epilogue
    gemm_hf<1, 1, 1><<<dim3(NB / 128, Td / 128), 256, SM_MAIN>>>(
        F1h, NUL_H, KV1th, NUL_H, Q2, base1, NUL_I, (float*)0, Y1h, (unsigned*)0,
        (float*)0, Tp, Tp, Tp, 0);
    gemm_hf<1, 1, 1><<<dim3(NB / 128, Tp / 128), 256, SM_MAIN>>>(
        F2h, NUL_H, KV2th, NUL_H, Q1, base2, NUL_I, (float*)0, Y2h, (unsigned*)0,
        (float*)0, Td, Td, Td, 0);

    // output projections (single product) with fused masked-max
    gemm_hf<1, 1, 2><<<dim3(1, (Bn * Td) / 128), 256, SM_OUT>>>(
        Y1h, NUL_H, Wodh, NUL_H, NUL_F, NUL_F, smask, (float*)0, (__half*)0, ob1,
        (float*)0, 128, 128, 128, Td);
    gemm_hf<1, 1, 2><<<dim3(1, (Bn * Tp) / 128), 256, SM_OUT>>>(
        Y2h, NUL_H, Woph, NUL_H, NUL_F, NUL_F, pmask, (float*)0, (__half*)0, ob2,
        (float*)0, 128, 128, 128, Tp);

    // decode + add output bias
    k_out<<<(Bn * 128 + 255) / 256, 256>>>(ob1, ob2, bpd, bpp, out);
}

// round 12
// speedup vs baseline: 2.4677x; 1.3801x over previous
#include <cuda_runtime.h>
#include <cuda_fp16.h>
#include <math.h>
#include <stdint.h>

// Problem constants
#define Bn   64
#define Td   256
#define Tp   1024
#define NB   (Bn * 256)
#define NEGV (-1e9f)
#define AL   __align__(256)

// ---------------- device scratch ----------------
__device__ AL __half g_F1h[Td * Tp];
__device__ AL __half g_F2h[Tp * Td];
__device__ AL __half g_Xph[Bn * Tp * 128];
__device__ AL __half g_Xsh[Bn * Td * 128];
__device__ AL __half g_Wp1h[384 * 128];     // rows: k0,v0,k1,v1,...,q0..q127
__device__ AL __half g_Wp2h[384 * 128];
__device__ AL float g_bp1[384], g_bp2[384];
__device__ AL __half g_Wodh[128 * 128];
__device__ AL __half g_Woph[128 * 128];
__device__ AL float g_Q1[Bn * Tp * 128];    // dense q projections
__device__ AL float g_Q2[Bn * Td * 128];
__device__ AL __half g_KV1th[NB * Tp];      // rows b*256+2d(ev)/2d+1(e), cols j
__device__ AL __half g_KV2th[NB * Td];
__device__ AL float g_base1[NB], g_base2[NB];   // interleaved [b*256 + 2d + {0,1}]
__device__ AL __half g_Y1h[Bn * Td * 128];
__device__ AL __half g_Y2h[Bn * Tp * 128];
__device__ AL unsigned g_ob1[Bn * 128], g_ob2[Bn * 128];

// ---------------- helpers ----------------
__device__ __forceinline__ unsigned f2key(float f) {
    unsigned u = __float_as_uint(f);
    return (u & 0x80000000u) ? ~u : (u | 0x80000000u);
}
__device__ __forceinline__ float key2f(unsigned u) {
    unsigned b = (u & 0x80000000u) ? (u ^ 0x80000000u) : ~u;
    return __uint_as_float(b);
}
__device__ __forceinline__ void mma16816(float* d, const uint32_t* a,
                                         uint32_t b0, uint32_t b1) {
    asm volatile(
        "mma.sync.aligned.m16n8k16.row.col.f32.f16.f16.f32 "
        "{%0,%1,%2,%3}, {%4,%5,%6,%7}, {%8,%9}, {%0,%1,%2,%3};"
        : "+f"(d[0]), "+f"(d[1]), "+f"(d[2]), "+f"(d[3])
        : "r"(a[0]), "r"(a[1]), "r"(a[2]), "r"(a[3]), "r"(b0), "r"(b1));
}
__device__ __forceinline__ void ldsm4(uint32_t* r, const __half* p) {
    uint32_t a = (uint32_t)__cvta_generic_to_shared(p);
    asm volatile("ldmatrix.sync.aligned.m8n8.x4.shared.b16 {%0,%1,%2,%3}, [%4];"
                 : "=r"(r[0]), "=r"(r[1]), "=r"(r[2]), "=r"(r[3]) : "r"(a));
}

// Per-direction GEMM argument bundle (merged dual launches)
struct GArgs {
    const __half* A;     // [M,K] fp16 row-major
    const __half* B;     // [N,K] fp16 row-major
    const float*  F0;    // MODE1: dense q; MODE3: packed bias
    const float*  F1;    // MODE1: base
    const int*    I;     // mask
    float*        oF;    // MODE3: dense q out
    __half*       oH;    // MODE1: Y out; MODE3: KV out
    unsigned*     oU;    // MODE2: ob
    float*        oB;    // MODE3: base sums
    int K, lda, ldb, ldx, Mtot;
};

// ---------------- fp16 tensor-core GEMM (single product), fused epilogues ----
// Dual-problem launch: blockIdx.y < ysplit -> g1, else g2.
// MODE 1: fused AFT y: acc pairs (num,den); y=sigmoid(q)*(num+bs)/(den+bs);
//         smem-staged coalesced fp16 Y writeout.
// MODE 2: fused masked max -> atomicMax oU (I=mask, ldx=SEQ).
// MODE 3: fused projection epilogue (ldx=SEQ). bcol<256: (k,v) col pairs ->
//         e=mask*exp(k+bk), ev=e*(v+bv); fp32 col-sum atomics; smem transpose ->
//         coalesced fp16 KV. bcol==256: dense fp32 q + bias.
// Tile 128x128x32, 256 threads, 8 warps (4m x 2n), warp tile 32x64.
// smem: row r, 16B chunk c -> phys chunk = c ^ ((r>>1)&3). Dynamic smem.
template <int MODE>
__global__ __launch_bounds__(256, 2) void gemm_dual(GArgs g1, GArgs g2, int ysplit)
{
    extern __shared__ __align__(16) __half dsm[];
    __half* sA0 = dsm;
    __half* sB0 = dsm + 4096;

    GArgs a;
    int yb;
    if ((int)blockIdx.y < ysplit) { a = g1; yb = blockIdx.y; }
    else                          { a = g2; yb = blockIdx.y - ysplit; }

    const int tid  = threadIdx.x;
    const int lane = tid & 31;
    const int wid  = tid >> 5;
    const int wm   = (wid >> 1) * 32;
    const int wn   = (wid & 1) * 64;
    const int brow = yb * 128;
    const int bcol = blockIdx.x * 128;

    const int lr  = tid >> 2;
    const int lc  = tid & 3;
    const int so0 = lr * 32 + ((lc ^ ((lr >> 1) & 3)) * 8);
    const int so1 = (lr + 64) * 32 + ((lc ^ (((lr + 64) >> 1) & 3)) * 8);

    const __half* gA0 = a.A + (size_t)(brow + lr) * a.lda + lc * 8;
    const __half* gB0 = a.B + (size_t)(bcol + lr) * a.ldb + lc * 8;
    const size_t a64 = (size_t)64 * a.lda, b64 = (size_t)64 * a.ldb;

    uint4 ra0[2], rb0[2];
    ra0[0] = *(const uint4*)(gA0); ra0[1] = *(const uint4*)(gA0 + a64);
    rb0[0] = *(const uint4*)(gB0); rb0[1] = *(const uint4*)(gB0 + b64);

    float acc[2][8][4] = {};

    const int arow_b = (lane & 7) + ((lane >> 3) & 1) * 8;
    const int achk_b = (lane >> 4);
    const int brow_b = (lane & 7) + (lane >> 4) * 8;
    const int bchk_b = (lane >> 3) & 1;

    for (int k0 = 0; k0 < a.K; k0 += 32) {
        *(uint4*)&sA0[so0] = ra0[0]; *(uint4*)&sA0[so1] = ra0[1];
        *(uint4*)&sB0[so0] = rb0[0]; *(uint4*)&sB0[so1] = rb0[1];
        __syncthreads();

        if (k0 + 32 < a.K) {
            ra0[0] = *(const uint4*)(gA0 + k0 + 32);
            ra0[1] = *(const uint4*)(gA0 + a64 + k0 + 32);
            rb0[0] = *(const uint4*)(gB0 + k0 + 32);
            rb0[1] = *(const uint4*)(gB0 + b64 + k0 + 32);
        }

        #pragma unroll
        for (int ck = 0; ck < 2; ck++) {
            uint32_t af[2][4];
            #pragma unroll
            for (int mt = 0; mt < 2; mt++) {
                int row = wm + mt * 16 + arow_b;
                int chk = 2 * ck + achk_b;
                int off = row * 32 + ((chk ^ ((row >> 1) & 3)) * 8);
                ldsm4(af[mt], &sA0[off]);
            }
            #pragma unroll
            for (int ntp = 0; ntp < 4; ntp++) {
                int row = wn + ntp * 16 + brow_b;
                int chk = 2 * ck + bchk_b;
                int off = row * 32 + ((chk ^ ((row >> 1) & 3)) * 8);
                uint32_t bf0[4];
                ldsm4(bf0, &sB0[off]);
                #pragma unroll
                for (int mt = 0; mt < 2; mt++) {
                    mma16816(acc[mt][2 * ntp],     af[mt], bf0[0], bf0[1]);
                    mma16816(acc[mt][2 * ntp + 1], af[mt], bf0[2], bf0[3]);
                }
            }
        }
        __syncthreads();
    }

    const int g = lane >> 2;
    const int c = lane & 3;

    if (MODE == 1) {
        const int b  = bcol >> 8;
        const int d0 = (bcol & 128) >> 1;     // 0 or 64
        __half* sy = dsm;                     // [128][72] staging
        #pragma unroll
        for (int mt = 0; mt < 2; mt++) {
            #pragma unroll
            for (int nt = 0; nt < 8; nt++) {
                int col = bcol + wn + nt * 8 + 2 * c;
                int d = (col & 255) >> 1;
                int dl = (wn + nt * 8 + 2 * c) >> 1;   // 0..63
                float2 bs = *(const float2*)&a.F1[col];
                #pragma unroll
                for (int r2 = 0; r2 < 2; r2++) {
                    int rowl = wm + mt * 16 + g + 8 * r2;
                    int rr = brow + rowl;
                    float num = acc[mt][nt][2 * r2]     + bs.x;
                    float den = acc[mt][nt][2 * r2 + 1] + bs.y;
                    float q = a.F0[((size_t)b * a.Mtot + rr) * 128 + d];
                    float sg = 1.f / (1.f + expf(-q));
                    sy[rowl * 72 + dl] = __float2half(sg * num / den);
                }
            }
        }
        __syncthreads();
        // coalesced writeout: 2 threads per row, 64B each
        int rl = tid >> 1, part = (tid & 1) * 32;
        const __half* src = &sy[rl * 72 + part];
        __half* dst = a.oH + ((size_t)b * a.Mtot + brow + rl) * 128 + d0 + part;
        #pragma unroll
        for (int u = 0; u < 4; u++)
            *(uint4*)(dst + 8 * u) = *(const uint4*)(src + 8 * u);
    } else if (MODE == 2) {
        const int SEQ = a.ldx;
        const int b = brow / SEQ;
        int msk[2][2];
        #pragma unroll
        for (int mt = 0; mt < 2; mt++) {
            msk[mt][0] = a.I[brow + wm + mt * 16 + g];
            msk[mt][1] = a.I[brow + wm + mt * 16 + g + 8];
        }
        #pragma unroll
        for (int nt = 0; nt < 8; nt++) {
            float m0 = -3.0e38f, m1 = -3.0e38f;
            #pragma unroll
            for (int mt = 0; mt < 2; mt++) {
                if (msk[mt][0]) { m0 = fmaxf(m0, acc[mt][nt][0]); m1 = fmaxf(m1, acc[mt][nt][1]); }
                if (msk[mt][1]) { m0 = fmaxf(m0, acc[mt][nt][2]); m1 = fmaxf(m1, acc[mt][nt][3]); }
            }
            #pragma unroll
            for (int off = 4; off < 32; off <<= 1) {
                m0 = fmaxf(m0, __shfl_xor_sync(0xffffffffu, m0, off));
                m1 = fmaxf(m1, __shfl_xor_sync(0xffffffffu, m1, off));
            }
            if (g == 0) {
                int col = wn + nt * 8 + 2 * c;
                if (m0 > -2.9e38f) atomicMax(&a.oU[b * 128 + col],     f2key(m0));
                if (m1 > -2.9e38f) atomicMax(&a.oU[b * 128 + col + 1], f2key(m1));
            }
        }
    } else {
        // MODE 3: fused projection epilogue
        const int SEQ = a.ldx;
        const int b   = brow / SEQ;
        const int j0  = brow - b * SEQ;
        __half* st = dsm;   // [128][136] transpose buffer (overlaps loop smem)
        if (bcol < 256) {
            __syncthreads();
            int msk[2][2];
            #pragma unroll
            for (int mt = 0; mt < 2; mt++) {
                msk[mt][0] = a.I[brow + wm + mt * 16 + g];
                msk[mt][1] = a.I[brow + wm + mt * 16 + g + 8];
            }
            #pragma unroll
            for (int nt = 0; nt < 8; nt++) {
                int colp = wn + nt * 8 + 2 * c;   // local even col (k)
                int dl   = colp >> 1;             // 0..63
                float bk = a.F0[bcol + colp];
                float bv = a.F0[bcol + colp + 1];
                float sev = 0.f, se = 0.f;
                #pragma unroll
                for (int mt = 0; mt < 2; mt++) {
                    #pragma unroll
                    for (int r2 = 0; r2 < 2; r2++) {
                        int rowl = wm + mt * 16 + g + 8 * r2;
                        float kk = acc[mt][nt][2 * r2]     + bk;
                        float vv = acc[mt][nt][2 * r2 + 1] + bv;
                        float e  = msk[mt][r2] ? expf(kk) : 0.f;
                        float ev = e * vv;
                        sev += ev; se += e;
                        st[(2 * dl)     * 136 + rowl] = __float2half(ev);
                        st[(2 * dl + 1) * 136 + rowl] = __float2half(e);
                    }
                }
                sev += __shfl_xor_sync(0xffffffffu, sev, 4);
                se  += __shfl_xor_sync(0xffffffffu, se, 4);
                sev += __shfl_xor_sync(0xffffffffu, sev, 8);
                se  += __shfl_xor_sync(0xffffffffu, se, 8);
                sev += __shfl_xor_sync(0xffffffffu, sev, 16);
                se  += __shfl_xor_sync(0xffffffffu, se, 16);
                if (g == 0) {
                    atomicAdd(&a.oB[b * 256 + bcol + 2 * dl],     sev);
                    atomicAdd(&a.oB[b * 256 + bcol + 2 * dl + 1], se);
                }
            }
            __syncthreads();
            int rl = tid >> 1, jh = (tid & 1) * 64;
            const __half* src = &st[rl * 136 + jh];
            __half* dst = a.oH + ((size_t)(b * 256 + bcol + rl)) * SEQ + j0 + jh;
            #pragma unroll
            for (int u = 0; u < 8; u++)
                *(uint4*)(dst + 8 * u) = *(const uint4*)(src + 8 * u);
        } else {
            // q part -> dense fp32 [row*128 + qd]
            #pragma unroll
            for (int mt = 0; mt < 2; mt++) {
                #pragma unroll
                for (int nt = 0; nt < 8; nt++) {
                    int colp = wn + nt * 8 + 2 * c;
                    float bx = a.F0[256 + colp], by = a.F0[256 + colp + 1];
                    int row = brow + wm + mt * 16 + g;
                    float2 v0, v1;
                    v0.x = acc[mt][nt][0] + bx; v0.y = acc[mt][nt][1] + by;
                    v1.x = acc[mt][nt][2] + bx; v1.y = acc[mt][nt][3] + by;
                    *(float2*)&a.oF[(size_t)row * 128 + colp]       = v0;
                    *(float2*)&a.oF[(size_t)(row + 8) * 128 + colp] = v1;
                }
            }
        }
    }
}

// ---------------- small kernels ----------------
__global__ void k_init(unsigned* ob1, unsigned* ob2, float* base1, float* base2) {
    int i = blockIdx.x * 256 + threadIdx.x;
    if (i < Bn * 128) {
        unsigned k = f2key(NEGV);
        ob1[i] = k; ob2[i] = k;
    }
    if (i < NB) { base1[i] = 0.f; base2[i] = 0.f; }
}

__global__ void k_expf(const float* __restrict__ pb, __half* __restrict__ F1,
                       __half* __restrict__ F2) {
    __shared__ float s[32][33];
    int j0 = blockIdx.x * 32, i0 = blockIdx.y * 32;
    int tx = threadIdx.x & 31, ty = threadIdx.x >> 5;
    #pragma unroll
    for (int r = ty; r < 32; r += 8) {
        float v = expf(pb[(i0 + r) * 1024 + j0 + tx]) - 1.0f;
        F1[(i0 + r) * Tp + j0 + tx] = __float2half(v);
        s[r][tx] = v;
    }
    __syncthreads();
    #pragma unroll
    for (int r = ty; r < 32; r += 8)
        F2[(j0 + r) * Td + i0 + tx] = __float2half(s[tx][r]);
}

// fp32 -> fp16 convert; 8 floats per thread, 16B stores
__global__ void k_half(const float* __restrict__ x, __half* __restrict__ h, int n8) {
    int i = blockIdx.x * 256 + threadIdx.x;
    if (i >= n8) return;
    float4 v0 = ((const float4*)x)[2 * i];
    float4 v1 = ((const float4*)x)[2 * i + 1];
    uint32_t hh[4];
    __half2 p;
    p = __floats2half2_rn(v0.x, v0.y); hh[0] = *(uint32_t*)&p;
    p = __floats2half2_rn(v0.z, v0.w); hh[1] = *(uint32_t*)&p;
    p = __floats2half2_rn(v1.x, v1.y); hh[2] = *(uint32_t*)&p;
    p = __floats2half2_rn(v1.z, v1.w); hh[3] = *(uint32_t*)&p;
    ((uint4*)h)[i] = make_uint4(hh[0], hh[1], hh[2], hh[3]);
}

// pack W rows interleaved fp16: r<256: even=k[r/2], odd=v[r/2]; r>=256: q[r-256]
__global__ void k_pack_half(const float* __restrict__ Wk, const float* __restrict__ bk,
                            const float* __restrict__ Wv, const float* __restrict__ bv,
                            const float* __restrict__ Wq, const float* __restrict__ bq,
                            __half* __restrict__ Wh, float* __restrict__ bp) {
    int i = blockIdx.x * 256 + threadIdx.x;
    if (i < 384 * 128) {
        int r = i >> 7, cc = i & 127;
        const float* s;
        int sr;
        if (r < 256) { s = (r & 1) ? Wv : Wk; sr = r >> 1; }
        else         { s = Wq; sr = r - 256; }
        Wh[i] = __float2half(s[sr * 128 + cc]);
    }
    if (i < 384) {
        bp[i] = (i < 256) ? ((i & 1) ? bv[i >> 1] : bk[i >> 1]) : bq[i - 256];
    }
}

__global__ void k_out(const unsigned* __restrict__ ob1, const unsigned* __restrict__ ob2,
                      const float* __restrict__ bpd, const float* __restrict__ bpp,
                      float* __restrict__ out) {
    int i = blockIdx.x * 256 + threadIdx.x;
    if (i < Bn * 128) {
        int t = i & 127;
        out[i]            = key2f(ob1[i]) + bpd[t];
        out[Bn * 128 + i] = key2f(ob2[i]) + bpp[t];
    }
}

// ---------------- launch ----------------
#define SYM(p, s) cudaGetSymbolAddress((void**)&p, s)

extern "C" void kernel_launch(void* const* d_in, const int* in_sizes, int n_in,
                              void* d_out, int out_size) {
    const float* smiles  = (const float*)d_in[0];
    const float* protein = (const float*)d_in[1];
    const int*   smask   = (const int*)d_in[2];
    const int*   pmask   = (const int*)d_in[3];
    const float* pb      = (const float*)d_in[4];
    const float* Wqd = (const float*)d_in[5],  *bqd = (const float*)d_in[6];
    const float* Wkp = (const float*)d_in[7],  *bkp = (const float*)d_in[8];
    const float* Wvp = (const float*)d_in[9],  *bvp = (const float*)d_in[10];
    const float* Wqp = (const float*)d_in[11], *bqp = (const float*)d_in[12];
    const float* Wkd = (const float*)d_in[13], *bkd = (const float*)d_in[14];
    const float* Wvd = (const float*)d_in[15], *bvd = (const float*)d_in[16];
    const float* Wpd = (const float*)d_in[17], *bpd = (const float*)d_in[18];
    const float* Wpp = (const float*)d_in[19], *bpp = (const float*)d_in[20];
    float* out = (float*)d_out;

    __half *F1h, *F2h, *Xph, *Xsh, *Wp1h, *Wp2h;
    __half *Wodh, *Woph, *KV1th, *KV2th, *Y1h, *Y2h;
    float *bp1, *bp2, *Q1, *Q2, *base1, *base2;
    unsigned *ob1, *ob2;
    SYM(F1h, g_F1h);   SYM(F2h, g_F2h);
    SYM(Xph, g_Xph);   SYM(Xsh, g_Xsh);
    SYM(Wp1h, g_Wp1h); SYM(Wp2h, g_Wp2h);
    SYM(bp1, g_bp1);   SYM(bp2, g_bp2);
    SYM(Wodh, g_Wodh); SYM(Woph, g_Woph);
    SYM(Q1, g_Q1);     SYM(Q2, g_Q2);
    SYM(KV1th, g_KV1th); SYM(KV2th, g_KV2th);
    SYM(base1, g_base1); SYM(base2, g_base2);
    SYM(Y1h, g_Y1h);   SYM(Y2h, g_Y2h);
    SYM(ob1, g_ob1);   SYM(ob2, g_ob2);

    const int SM_PROJ = 136 * 128 * 2;   // 34816 (MODE3 transpose buffer)
    const int SM_MAIN = 72 * 128 * 2;    // 18432 (MODE1 y staging; loop uses 16KB)
    const int SM_OUT  = 2 * 8192;        // 16384

    // init + batch-independent precompute
    k_init<<<NB / 256, 256>>>(ob1, ob2, base1, base2);
    k_expf<<<dim3(Tp / 32, Td / 32), 256>>>(pb, F1h, F2h);
    k_half<<<(Bn * Tp * 128 / 8 + 255) / 256, 256>>>(protein, Xph, Bn * Tp * 128 / 8);
    k_half<<<(Bn * Td * 128 / 8 + 255) / 256, 256>>>(smiles, Xsh, Bn * Td * 128 / 8);
    k_half<<<(128 * 128 / 8 + 255) / 256, 256>>>(Wpd, Wodh, 128 * 128 / 8);
    k_half<<<(128 * 128 / 8 + 255) / 256, 256>>>(Wpp, Woph, 128 * 128 / 8);
    k_pack_half<<<192, 256>>>(Wkp, bkp, Wvp, bvp, Wqp, bqp, Wp1h, bp1);
    k_pack_half<<<192, 256>>>(Wkd, bkd, Wvd, bvd, Wqd, bqd, Wp2h, bp2);

    GArgs z = {};

    // merged projections (MODE 3): protein (512 y-tiles) + smiles (128 y-tiles)
    {
        GArgs p1 = z, p2 = z;
        p1.A = Xph; p1.B = Wp1h; p1.F0 = bp1; p1.I = pmask;
        p1.oF = Q1; p1.oH = KV1th; p1.oB = base1;
        p1.K = 128; p1.lda = 128; p1.ldb = 128; p1.ldx = Tp; p1.Mtot = Tp;
        p2.A = Xsh; p2.B = Wp2h; p2.F0 = bp2; p2.I = smask;
        p2.oF = Q2; p2.oH = KV2th; p2.oB = base2;
        p2.K = 128; p2.lda = 128; p2.ldb = 128; p2.ldx = Td; p2.Mtot = Td;
        gemm_dual<3><<<dim3(3, 512 + 128), 256, SM_PROJ>>>(p1, p2, 512);
    }

    // merged main AFT GEMMs (MODE 1): dir1 heavy (K=1024, 2 y-tiles) first
    {
        GArgs m1 = z, m2 = z;
        m1.A = F1h; m1.B = KV1th; m1.F0 = Q2; m1.F1 = base1; m1.oH = Y1h;
        m1.K = Tp; m1.lda = Tp; m1.ldb = Tp; m1.Mtot = Td;
        m2.A = F2h; m2.B = KV2th; m2.F0 = Q1; m2.F1 = base2; m2.oH = Y2h;
        m2.K = Td; m2.lda = Td; m2.ldb = Td; m2.Mtot = Tp;
        gemm_dual<1><<<dim3(NB / 128, 2 + 8), 256, SM_MAIN>>>(m1, m2, 2);
    }

    // merged output projections (MODE 2) with fused masked-max
    {
        GArgs o1 = z, o2 = z;
        o1.A = Y1h; o1.B = Wodh; o1.I = smask; o1.oU = ob1;
        o1.K = 128; o1.lda = 128; o1.ldb = 128; o1.ldx = Td;
        o2.A = Y2h; o2.B = Woph; o2.I = pmask; o2.oU = ob2;
        o2.K = 128; o2.lda = 128; o2.ldb = 128; o2.ldx = Tp;
        gemm_dual<2><<<dim3(1, 128 + 512), 256, SM_OUT>>>(o1, o2, 128);
    }

    // decode + add output bias
    k_out<<<(Bn * 128 + 255) / 256, 256>>>(ob1, ob2, bpd, bpp, out);
}

// round 13
// speedup vs baseline: 2.5966x; 1.0523x over previous
#include <cuda_runtime.h>
#include <cuda_fp16.h>
#include <math.h>
#include <stdint.h>

// Problem constants
#define Bn   64
#define Td   256
#define Tp   1024
#define NB   (Bn * 256)
#define NEGV (-1e9f)
#define AL   __align__(256)

// ---------------- device scratch ----------------
__device__ AL __half g_F1h[Td * Tp];
__device__ AL __half g_F2h[Tp * Td];
__device__ AL __half g_Xph[Bn * Tp * 128];
__device__ AL __half g_Xsh[Bn * Td * 128];
__device__ AL __half g_Wp1h[384 * 128];     // rows: k0,v0,k1,v1,...,q0..q127
__device__ AL __half g_Wp2h[384 * 128];
__device__ AL float g_bp1[384], g_bp2[384];
__device__ AL __half g_Wodh[128 * 128];
__device__ AL __half g_Woph[128 * 128];
__device__ AL float g_Q1[Bn * Tp * 128];    // dense q projections
__device__ AL float g_Q2[Bn * Td * 128];
__device__ AL __half g_KV1th[NB * Tp];      // rows b*256+2d(ev)/2d+1(e), cols j
__device__ AL __half g_KV2th[NB * Td];
__device__ AL float g_base1[NB], g_base2[NB];   // interleaved [b*256 + 2d + {0,1}]
__device__ AL __half g_Y1h[Bn * Td * 128];
__device__ AL __half g_Y2h[Bn * Tp * 128];
__device__ AL unsigned g_ob1[Bn * 128], g_ob2[Bn * 128];

// ---------------- helpers ----------------
__device__ __forceinline__ unsigned f2key(float f) {
    unsigned u = __float_as_uint(f);
    return (u & 0x80000000u) ? ~u : (u | 0x80000000u);
}
__device__ __forceinline__ float key2f(unsigned u) {
    unsigned b = (u & 0x80000000u) ? (u ^ 0x80000000u) : ~u;
    return __uint_as_float(b);
}
__device__ __forceinline__ void mma16816(float* d, const uint32_t* a,
                                         uint32_t b0, uint32_t b1) {
    asm volatile(
        "mma.sync.aligned.m16n8k16.row.col.f32.f16.f16.f32 "
        "{%0,%1,%2,%3}, {%4,%5,%6,%7}, {%8,%9}, {%0,%1,%2,%3};"
        : "+f"(d[0]), "+f"(d[1]), "+f"(d[2]), "+f"(d[3])
        : "r"(a[0]), "r"(a[1]), "r"(a[2]), "r"(a[3]), "r"(b0), "r"(b1));
}
__device__ __forceinline__ void ldsm4(uint32_t* r, const __half* p) {
    uint32_t a = (uint32_t)__cvta_generic_to_shared(p);
    asm volatile("ldmatrix.sync.aligned.m8n8.x4.shared.b16 {%0,%1,%2,%3}, [%4];"
                 : "=r"(r[0]), "=r"(r[1]), "=r"(r[2]), "=r"(r[3]) : "r"(a));
}

// Per-direction GEMM argument bundle (merged dual launches)
struct GArgs {
    const __half* A;     // [M,K] fp16 row-major
    const __half* B;     // [N,K] fp16 row-major
    const float*  F0;    // MODE1: dense q; MODE3: packed bias
    const float*  F1;    // MODE1: base
    const int*    I;     // mask
    float*        oF;    // MODE3: dense q out
    __half*       oH;    // MODE1: Y out; MODE3: KV out
    unsigned*     oU;    // MODE2: ob
    float*        oB;    // MODE3: base sums
    int K, lda, ldb, ldx, Mtot;
};

// ---------------- fp16 tensor-core GEMM (single product), fused epilogues ----
// Dual-problem launch: blockIdx.y < ysplit -> g1, else g2.
// Double-buffered smem stages (2 x 16KB), ONE barrier per k-iter.
// MODE 1: fused AFT y epilogue; smem-staged coalesced fp16 Y writeout.
// MODE 2: fused masked max -> atomicMax oU (I=mask, ldx=SEQ).
// MODE 3: fused projection epilogue (KV build + base sums + dense q).
// Tile 128x128x32, 256 threads, 8 warps (4m x 2n), warp tile 32x64.
// smem: row r, 16B chunk c -> phys chunk = c ^ ((r>>1)&3).
template <int MODE>
__global__ __launch_bounds__(256, 2) void gemm_dual(GArgs g1, GArgs g2, int ysplit)
{
    extern __shared__ __align__(16) __half dsm[];

    GArgs a;
    int yb;
    if ((int)blockIdx.y < ysplit) { a = g1; yb = blockIdx.y; }
    else                          { a = g2; yb = blockIdx.y - ysplit; }

    const int tid  = threadIdx.x;
    const int lane = tid & 31;
    const int wid  = tid >> 5;
    const int wm   = (wid >> 1) * 32;
    const int wn   = (wid & 1) * 64;
    const int brow = yb * 128;
    const int bcol = blockIdx.x * 128;

    const int lr  = tid >> 2;
    const int lc  = tid & 3;
    const int so0 = lr * 32 + ((lc ^ ((lr >> 1) & 3)) * 8);
    const int so1 = (lr + 64) * 32 + ((lc ^ (((lr + 64) >> 1) & 3)) * 8);

    const __half* gA0 = a.A + (size_t)(brow + lr) * a.lda + lc * 8;
    const __half* gB0 = a.B + (size_t)(bcol + lr) * a.ldb + lc * 8;
    const size_t a64 = (size_t)64 * a.lda, b64 = (size_t)64 * a.ldb;

    uint4 ra0[2], rb0[2];
    ra0[0] = *(const uint4*)(gA0); ra0[1] = *(const uint4*)(gA0 + a64);
    rb0[0] = *(const uint4*)(gB0); rb0[1] = *(const uint4*)(gB0 + b64);

    float acc[2][8][4] = {};

    const int arow_b = (lane & 7) + ((lane >> 3) & 1) * 8;
    const int achk_b = (lane >> 4);
    const int brow_b = (lane & 7) + (lane >> 4) * 8;
    const int bchk_b = (lane >> 3) & 1;

    const int iters = a.K >> 5;
    for (int i = 0; i < iters; i++) {
        const int k0 = 32 * i;
        __half* sA0 = dsm + (i & 1) * 8192;      // stage: A at +0, B at +4096
        __half* sB0 = sA0 + 4096;
        *(uint4*)&sA0[so0] = ra0[0]; *(uint4*)&sA0[so1] = ra0[1];
        *(uint4*)&sB0[so0] = rb0[0]; *(uint4*)&sB0[so1] = rb0[1];
        __syncthreads();

        if (k0 + 32 < a.K) {
            ra0[0] = *(const uint4*)(gA0 + k0 + 32);
            ra0[1] = *(const uint4*)(gA0 + a64 + k0 + 32);
            rb0[0] = *(const uint4*)(gB0 + k0 + 32);
            rb0[1] = *(const uint4*)(gB0 + b64 + k0 + 32);
        }

        #pragma unroll
        for (int ck = 0; ck < 2; ck++) {
            uint32_t af[2][4];
            #pragma unroll
            for (int mt = 0; mt < 2; mt++) {
                int row = wm + mt * 16 + arow_b;
                int chk = 2 * ck + achk_b;
                int off = row * 32 + ((chk ^ ((row >> 1) & 3)) * 8);
                ldsm4(af[mt], &sA0[off]);
            }
            #pragma unroll
            for (int ntp = 0; ntp < 4; ntp++) {
                int row = wn + ntp * 16 + brow_b;
                int chk = 2 * ck + bchk_b;
                int off = row * 32 + ((chk ^ ((row >> 1) & 3)) * 8);
                uint32_t bf0[4];
                ldsm4(bf0, &sB0[off]);
                #pragma unroll
                for (int mt = 0; mt < 2; mt++) {
                    mma16816(acc[mt][2 * ntp],     af[mt], bf0[0], bf0[1]);
                    mma16816(acc[mt][2 * ntp + 1], af[mt], bf0[2], bf0[3]);
                }
            }
        }
    }

    const int g = lane >> 2;
    const int c = lane & 3;

    if (MODE == 1) {
        __syncthreads();                      // all warps past last compute
        const int b  = bcol >> 8;
        const int d0 = (bcol & 128) >> 1;     // 0 or 64
        __half* sy = dsm;                     // [128][72] staging
        #pragma unroll
        for (int mt = 0; mt < 2; mt++) {
            #pragma unroll
            for (int nt = 0; nt < 8; nt++) {
                int col = bcol + wn + nt * 8 + 2 * c;
                int d = (col & 255) >> 1;
                int dl = (wn + nt * 8 + 2 * c) >> 1;   // 0..63
                float2 bs = *(const float2*)&a.F1[col];
                #pragma unroll
                for (int r2 = 0; r2 < 2; r2++) {
                    int rowl = wm + mt * 16 + g + 8 * r2;
                    int rr = brow + rowl;
                    float num = acc[mt][nt][2 * r2]     + bs.x;
                    float den = acc[mt][nt][2 * r2 + 1] + bs.y;
                    float q = a.F0[((size_t)b * a.Mtot + rr) * 128 + d];
                    float sg = 1.f / (1.f + expf(-q));
                    sy[rowl * 72 + dl] = __float2half(sg * num / den);
                }
            }
        }
        __syncthreads();
        int rl = tid >> 1, part = (tid & 1) * 32;
        const __half* src = &sy[rl * 72 + part];
        __half* dst = a.oH + ((size_t)b * a.Mtot + brow + rl) * 128 + d0 + part;
        #pragma unroll
        for (int u = 0; u < 4; u++)
            *(uint4*)(dst + 8 * u) = *(const uint4*)(src + 8 * u);
    } else if (MODE == 2) {
        const int SEQ = a.ldx;
        const int b = brow / SEQ;
        int msk[2][2];
        #pragma unroll
        for (int mt = 0; mt < 2; mt++) {
            msk[mt][0] = a.I[brow + wm + mt * 16 + g];
            msk[mt][1] = a.I[brow + wm + mt * 16 + g + 8];
        }
        #pragma unroll
        for (int nt = 0; nt < 8; nt++) {
            float m0 = -3.0e38f, m1 = -3.0e38f;
            #pragma unroll
            for (int mt = 0; mt < 2; mt++) {
                if (msk[mt][0]) { m0 = fmaxf(m0, acc[mt][nt][0]); m1 = fmaxf(m1, acc[mt][nt][1]); }
                if (msk[mt][1]) { m0 = fmaxf(m0, acc[mt][nt][2]); m1 = fmaxf(m1, acc[mt][nt][3]); }
            }
            #pragma unroll
            for (int off = 4; off < 32; off <<= 1) {
                m0 = fmaxf(m0, __shfl_xor_sync(0xffffffffu, m0, off));
                m1 = fmaxf(m1, __shfl_xor_sync(0xffffffffu, m1, off));
            }
            if (g == 0) {
                int col = wn + nt * 8 + 2 * c;
                if (m0 > -2.9e38f) atomicMax(&a.oU[b * 128 + col],     f2key(m0));
                if (m1 > -2.9e38f) atomicMax(&a.oU[b * 128 + col + 1], f2key(m1));
            }
        }
    } else {
        // MODE 3: fused projection epilogue
        const int SEQ = a.ldx;
        const int b   = brow / SEQ;
        const int j0  = brow - b * SEQ;
        __half* st = dsm;   // [128][136] transpose buffer (overlaps loop smem)
        if (bcol < 256) {
            __syncthreads();
            int msk[2][2];
            #pragma unroll
            for (int mt = 0; mt < 2; mt++) {
                msk[mt][0] = a.I[brow + wm + mt * 16 + g];
                msk[mt][1] = a.I[brow + wm + mt * 16 + g + 8];
            }
            #pragma unroll
            for (int nt = 0; nt < 8; nt++) {
                int colp = wn + nt * 8 + 2 * c;   // local even col (k)
                int dl   = colp >> 1;             // 0..63
                float bk = a.F0[bcol + colp];
                float bv = a.F0[bcol + colp + 1];
                float sev = 0.f, se = 0.f;
                #pragma unroll
                for (int mt = 0; mt < 2; mt++) {
                    #pragma unroll
                    for (int r2 = 0; r2 < 2; r2++) {
                        int rowl = wm + mt * 16 + g + 8 * r2;
                        float kk = acc[mt][nt][2 * r2]     + bk;
                        float vv = acc[mt][nt][2 * r2 + 1] + bv;
                        float e  = msk[mt][r2] ? expf(kk) : 0.f;
                        float ev = e * vv;
                        sev += ev; se += e;
                        st[(2 * dl)     * 136 + rowl] = __float2half(ev);
                        st[(2 * dl + 1) * 136 + rowl] = __float2half(e);
                    }
                }
                sev += __shfl_xor_sync(0xffffffffu, sev, 4);
                se  += __shfl_xor_sync(0xffffffffu, se, 4);
                sev += __shfl_xor_sync(0xffffffffu, sev, 8);
                se  += __shfl_xor_sync(0xffffffffu, se, 8);
                sev += __shfl_xor_sync(0xffffffffu, sev, 16);
                se  += __shfl_xor_sync(0xffffffffu, se, 16);
                if (g == 0) {
                    atomicAdd(&a.oB[b * 256 + bcol + 2 * dl],     sev);
                    atomicAdd(&a.oB[b * 256 + bcol + 2 * dl + 1], se);
                }
            }
            __syncthreads();
            int rl = tid >> 1, jh = (tid & 1) * 64;
            const __half* src = &st[rl * 136 + jh];
            __half* dst = a.oH + ((size_t)(b * 256 + bcol + rl)) * SEQ + j0 + jh;
            #pragma unroll
            for (int u = 0; u < 8; u++)
                *(uint4*)(dst + 8 * u) = *(const uint4*)(src + 8 * u);
        } else {
            // q part -> dense fp32 [row*128 + qd]
            #pragma unroll
            for (int mt = 0; mt < 2; mt++) {
                #pragma unroll
                for (int nt = 0; nt < 8; nt++) {
                    int colp = wn + nt * 8 + 2 * c;
                    float bx = a.F0[256 + colp], by = a.F0[256 + colp + 1];
                    int row = brow + wm + mt * 16 + g;
                    float2 v0, v1;
                    v0.x = acc[mt][nt][0] + bx; v0.y = acc[mt][nt][1] + by;
                    v1.x = acc[mt][nt][2] + bx; v1.y = acc[mt][nt][3] + by;
                    *(float2*)&a.oF[(size_t)row * 128 + colp]       = v0;
                    *(float2*)&a.oF[(size_t)(row + 8) * 128 + colp] = v1;
                }
            }
        }
    }
}

// ---------------- mega prep kernel (all independent elementwise work) ----------
// blocks: [0,64) init | [64,320) expf | [320,4416) half(protein) |
// [4416,5440) half(smiles) | [5440,5448) half(Wpd) | [5448,5456) half(Wpp) |
// [5456,5648) pack1 | [5648,5840) pack2
__device__ __forceinline__ void prep_half(const float* x, __half* h, int i, int n8) {
    if (i >= n8) return;
    float4 v0 = ((const float4*)x)[2 * i];
    float4 v1 = ((const float4*)x)[2 * i + 1];
    uint32_t hh[4];
    __half2 p;
    p = __floats2half2_rn(v0.x, v0.y); hh[0] = *(uint32_t*)&p;
    p = __floats2half2_rn(v0.z, v0.w); hh[1] = *(uint32_t*)&p;
    p = __floats2half2_rn(v1.x, v1.y); hh[2] = *(uint32_t*)&p;
    p = __floats2half2_rn(v1.z, v1.w); hh[3] = *(uint32_t*)&p;
    ((uint4*)h)[i] = make_uint4(hh[0], hh[1], hh[2], hh[3]);
}
__device__ __forceinline__ void prep_pack(const float* Wk, const float* bk,
                                          const float* Wv, const float* bv,
                                          const float* Wq, const float* bq,
                                          __half* Wh, float* bp, int i) {
    if (i < 384 * 128) {
        int r = i >> 7, cc = i & 127;
        const float* s;
        int sr;
        if (r < 256) { s = (r & 1) ? Wv : Wk; sr = r >> 1; }
        else         { s = Wq; sr = r - 256; }
        Wh[i] = __float2half(s[sr * 128 + cc]);
    }
    if (i < 384) {
        bp[i] = (i < 256) ? ((i & 1) ? bv[i >> 1] : bk[i >> 1]) : bq[i - 256];
    }
}

__global__ void k_prep(
    const float* __restrict__ protein, const float* __restrict__ smiles,
    const float* __restrict__ pb,
    const float* Wkp, const float* bkp, const float* Wvp, const float* bvp,
    const float* Wqp, const float* bqp,
    const float* Wkd, const float* bkd, const float* Wvd, const float* bvd,
    const float* Wqd, const float* bqd,
    const float* Wpd, const float* Wpp,
    __half* Xph, __half* Xsh, __half* F1, __half* F2,
    __half* Wp1h, __half* Wp2h, float* bp1, float* bp2,
    __half* Wodh, __half* Woph,
    unsigned* ob1, unsigned* ob2, float* base1, float* base2)
{
    __shared__ float s[32][33];
    const int bid = blockIdx.x;
    const int tid = threadIdx.x;
    if (bid < 64) {
        int i = bid * 256 + tid;
        if (i < Bn * 128) {
            unsigned k = f2key(NEGV);
            ob1[i] = k; ob2[i] = k;
        }
        base1[i] = 0.f; base2[i] = 0.f;
    } else if (bid < 320) {
        int t = bid - 64;
        int j0 = (t & 31) * 32, i0 = (t >> 5) * 32;
        int tx = tid & 31, ty = tid >> 5;
        #pragma unroll
        for (int r = ty; r < 32; r += 8) {
            float v = expf(pb[(i0 + r) * 1024 + j0 + tx]) - 1.0f;
            F1[(i0 + r) * Tp + j0 + tx] = __float2half(v);
            s[r][tx] = v;
        }
        __syncthreads();
        #pragma unroll
        for (int r = ty; r < 32; r += 8)
            F2[(j0 + r) * Td + i0 + tx] = __float2half(s[tx][r]);
    } else if (bid < 4416) {
        prep_half(protein, Xph, (bid - 320) * 256 + tid, Bn * Tp * 128 / 8);
    } else if (bid < 5440) {
        prep_half(smiles, Xsh, (bid - 4416) * 256 + tid, Bn * Td * 128 / 8);
    } else if (bid < 5448) {
        prep_half(Wpd, Wodh, (bid - 5440) * 256 + tid, 128 * 128 / 8);
    } else if (bid < 5456) {
        prep_half(Wpp, Woph, (bid - 5448) * 256 + tid, 128 * 128 / 8);
    } else if (bid < 5648) {
        prep_pack(Wkp, bkp, Wvp, bvp, Wqp, bqp, Wp1h, bp1, (bid - 5456) * 256 + tid);
    } else {
        prep_pack(Wkd, bkd, Wvd, bvd, Wqd, bqd, Wp2h, bp2, (bid - 5648) * 256 + tid);
    }
}

__global__ void k_out(const unsigned* __restrict__ ob1, const unsigned* __restrict__ ob2,
                      const float* __restrict__ bpd, const float* __restrict__ bpp,
                      float* __restrict__ out) {
    int i = blockIdx.x * 256 + threadIdx.x;
    if (i < Bn * 128) {
        int t = i & 127;
        out[i]            = key2f(ob1[i]) + bpd[t];
        out[Bn * 128 + i] = key2f(ob2[i]) + bpp[t];
    }
}

// ---------------- launch ----------------
#define SYM(p, s) cudaGetSymbolAddress((void**)&p, s)

extern "C" void kernel_launch(void* const* d_in, const int* in_sizes, int n_in,
                              void* d_out, int out_size) {
    const float* smiles  = (const float*)d_in[0];
    const float* protein = (const float*)d_in[1];
    const int*   smask   = (const int*)d_in[2];
    const int*   pmask   = (const int*)d_in[3];
    const float* pb      = (const float*)d_in[4];
    const float* Wqd = (const float*)d_in[5],  *bqd = (const float*)d_in[6];
    const float* Wkp = (const float*)d_in[7],  *bkp = (const float*)d_in[8];
    const float* Wvp = (const float*)d_in[9],  *bvp = (const float*)d_in[10];
    const float* Wqp = (const float*)d_in[11], *bqp = (const float*)d_in[12];
    const float* Wkd = (const float*)d_in[13], *bkd = (const float*)d_in[14];
    const float* Wvd = (const float*)d_in[15], *bvd = (const float*)d_in[16];
    const float* Wpd = (const float*)d_in[17], *bpd = (const float*)d_in[18];
    const float* Wpp = (const float*)d_in[19], *bpp = (const float*)d_in[20];
    float* out = (float*)d_out;

    __half *F1h, *F2h, *Xph, *Xsh, *Wp1h, *Wp2h;
    __half *Wodh, *Woph, *KV1th, *KV2th, *Y1h, *Y2h;
    float *bp1, *bp2, *Q1, *Q2, *base1, *base2;
    unsigned *ob1, *ob2;
    SYM(F1h, g_F1h);   SYM(F2h, g_F2h);
    SYM(Xph, g_Xph);   SYM(Xsh, g_Xsh);
    SYM(Wp1h, g_Wp1h); SYM(Wp2h, g_Wp2h);
    SYM(bp1, g_bp1);   SYM(bp2, g_bp2);
    SYM(Wodh, g_Wodh); SYM(Woph, g_Woph);
    SYM(Q1, g_Q1);     SYM(Q2, g_Q2);
    SYM(KV1th, g_KV1th); SYM(KV2th, g_KV2th);
    SYM(base1, g_base1); SYM(base2, g_base2);
    SYM(Y1h, g_Y1h);   SYM(Y2h, g_Y2h);
    SYM(ob1, g_ob1);   SYM(ob2, g_ob2);

    const int SM_PROJ = 136 * 128 * 2;   // 34816 (MODE3 transpose; loop uses 32KB)
    const int SM_MAIN = 2 * 16384;       // 32768 (2 stages; MODE1 staging 18KB overlaps)
    const int SM_OUT  = 2 * 16384;       // 32768

    // one mega prep launch (init + expf + converts + packs)
    k_prep<<<5840, 256>>>(protein, smiles, pb,
                          Wkp, bkp, Wvp, bvp, Wqp, bqp,
                          Wkd, bkd, Wvd, bvd, Wqd, bqd,
                          Wpd, Wpp,
                          Xph, Xsh, F1h, F2h, Wp1h, Wp2h, bp1, bp2,
                          Wodh, Woph, ob1, ob2, base1, base2);

    GArgs z = {};

    // merged projections (MODE 3): protein (512 y-tiles) + smiles (128 y-tiles)
    {
        GArgs p1 = z, p2 = z;
        p1.A = Xph; p1.B = Wp1h; p1.F0 = bp1; p1.I = pmask;
        p1.oF = Q1; p1.oH = KV1th; p1.oB = base1;
        p1.K = 128; p1.lda = 128; p1.ldb = 128; p1.ldx = Tp; p1.Mtot = Tp;
        p2.A = Xsh; p2.B = Wp2h; p2.F0 = bp2; p2.I = smask;
        p2.oF = Q2; p2.oH = KV2th; p2.oB = base2;
        p2.K = 128; p2.lda = 128; p2.ldb = 128; p2.ldx = Td; p2.Mtot = Td;
        gemm_dual<3><<<dim3(3, 512 + 128), 256, SM_PROJ>>>(p1, p2, 512);
    }

    // merged main AFT GEMMs (MODE 1): dir1 heavy (K=1024, 2 y-tiles) first
    {
        GArgs m1 = z, m2 = z;
        m1.A = F1h; m1.B = KV1th; m1.F0 = Q2; m1.F1 = base1; m1.oH = Y1h;
        m1.K = Tp; m1.lda = Tp; m1.ldb = Tp; m1.Mtot = Td;
        m2.A = F2h; m2.B = KV2th; m2.F0 = Q1; m2.F1 = base2; m2.oH = Y2h;
        m2.K = Td; m2.lda = Td; m2.ldb = Td; m2.Mtot = Tp;
        gemm_dual<1><<<dim3(NB / 128, 2 + 8), 256, SM_MAIN>>>(m1, m2, 2);
    }

    // merged output projections (MODE 2) with fused masked-max
    {
        GArgs o1 = z, o2 = z;
        o1.A = Y1h; o1.B = Wodh; o1.I = smask; o1.oU = ob1;
        o1.K = 128; o1.lda = 128; o1.ldb = 128; o1.ldx = Td;
        o2.A = Y2h; o2.B = Woph; o2.I = pmask; o2.oU = ob2;
        o2.K = 128; o2.lda = 128; o2.ldb = 128; o2.ldx = Tp;
        gemm_dual<2><<<dim3(1, 128 + 512), 256, SM_OUT>>>(o1, o2, 128);
    }

    // decode + add output bias
    k_out<<<(Bn * 128 + 255) / 256, 256>>>(ob1, ob2, bpd, bpp, out);
}